// round 1
// baseline (speedup 1.0000x reference)
#include <cuda_runtime.h>
#include <math.h>

// Problem shape constants
#define Bn  8
#define Tn  512
#define En  1024
#define Hn  16
#define Dn  64
#define Ln  4
#define FFn 4096

// ---------------------------------------------------------------------------
// Scratch (device globals; no dynamic allocation allowed)
// ---------------------------------------------------------------------------
__device__ float g_x[Bn * Tn * En];            // activations (16 MB)
__device__ float g_qkv[Bn * Tn * 3 * En];      // qkv projection (48 MB)
__device__ float g_scores[Bn * Hn * Tn * Tn];  // attention scores (134 MB)
__device__ float g_attn[Bn * Tn * En];         // attention output, heads concat (16 MB)
__device__ float g_proj[Bn * Tn * En];         // proj / ff2 result (16 MB)
__device__ float g_ff[Bn * Tn * FFn];          // ff1 result (64 MB)

// ---------------------------------------------------------------------------
// Block reductions (256 threads = 8 warps)
// ---------------------------------------------------------------------------
__device__ __forceinline__ float warpReduceSum(float v) {
#pragma unroll
    for (int o = 16; o; o >>= 1) v += __shfl_xor_sync(0xffffffffu, v, o);
    return v;
}
__device__ __forceinline__ float warpReduceMax(float v) {
#pragma unroll
    for (int o = 16; o; o >>= 1) v = fmaxf(v, __shfl_xor_sync(0xffffffffu, v, o));
    return v;
}
__device__ __forceinline__ float blockReduceSum(float v) {
    __shared__ float sm[8];
    int lane = threadIdx.x & 31, wid = threadIdx.x >> 5;
    v = warpReduceSum(v);
    __syncthreads();              // WAR guard for sm reuse across calls
    if (lane == 0) sm[wid] = v;
    __syncthreads();
    v = sm[lane & 7];
#pragma unroll
    for (int o = 4; o; o >>= 1) v += __shfl_xor_sync(0xffffffffu, v, o);
    return v;
}
__device__ __forceinline__ float blockReduceMax(float v) {
    __shared__ float sm[8];
    int lane = threadIdx.x & 31, wid = threadIdx.x >> 5;
    v = warpReduceMax(v);
    __syncthreads();
    if (lane == 0) sm[wid] = v;
    __syncthreads();
    v = sm[lane & 7];
#pragma unroll
    for (int o = 4; o; o >>= 1) v = fmaxf(v, __shfl_xor_sync(0xffffffffu, v, o));
    return v;
}

// ---------------------------------------------------------------------------
// Positional encoding add: x[b,t,e] = src[b,t,e] + pe(b,e)
// pe(b,2i)   = sin(b * exp(-2i * ln(10000)/E))
// pe(b,2i+1) = cos(b * exp(-2i * ln(10000)/E))
// ---------------------------------------------------------------------------
__global__ void pe_add_kernel(const float* __restrict__ src, float* __restrict__ x) {
    int idx = blockIdx.x * 256 + threadIdx.x;
    int e = idx & (En - 1);
    int b = idx / (Tn * En);
    float dv = expf((float)(e & ~1) * (-9.210340371976184f / (float)En));
    float ang = (float)b * dv;
    float pe = (e & 1) ? cosf(ang) : sinf(ang);
    x[idx] = src[idx] + pe;
}

// ---------------------------------------------------------------------------
// SGEMM (NT): C[M,N] = A[M,K] @ B[N,K]^T + bias[N]  (optional relu)
// 128x128 tile, BK=16, 256 threads, 8x8 per-thread register blocking.
// M,N % 128 == 0, K % 16 == 0 required.
// ---------------------------------------------------------------------------
__global__ __launch_bounds__(256) void sgemm_nt(
    const float* __restrict__ A, const float* __restrict__ B,
    const float* __restrict__ bias, float* __restrict__ C,
    int M, int N, int K, int relu)
{
    __shared__ float As[16][128];
    __shared__ float Bs[16][128];

    const int tid  = threadIdx.x;
    const int lrow = tid >> 2;          // 0..63
    const int lcol = (tid & 3) << 2;    // 0,4,8,12
    const int tx   = tid & 15;
    const int ty   = tid >> 4;

    const float* Ab = A + (size_t)blockIdx.y * 128 * K;
    const float* Bb = B + (size_t)blockIdx.x * 128 * K;

    float acc[8][8] = {};

    for (int k0 = 0; k0 < K; k0 += 16) {
        float4 a0v = *(const float4*)(Ab + (size_t)lrow * K + k0 + lcol);
        float4 a1v = *(const float4*)(Ab + (size_t)(lrow + 64) * K + k0 + lcol);
        float4 b0v = *(const float4*)(Bb + (size_t)lrow * K + k0 + lcol);
        float4 b1v = *(const float4*)(Bb + (size_t)(lrow + 64) * K + k0 + lcol);

        As[lcol + 0][lrow] = a0v.x; As[lcol + 1][lrow] = a0v.y;
        As[lcol + 2][lrow] = a0v.z; As[lcol + 3][lrow] = a0v.w;
        As[lcol + 0][lrow + 64] = a1v.x; As[lcol + 1][lrow + 64] = a1v.y;
        As[lcol + 2][lrow + 64] = a1v.z; As[lcol + 3][lrow + 64] = a1v.w;
        Bs[lcol + 0][lrow] = b0v.x; Bs[lcol + 1][lrow] = b0v.y;
        Bs[lcol + 2][lrow] = b0v.z; Bs[lcol + 3][lrow] = b0v.w;
        Bs[lcol + 0][lrow + 64] = b1v.x; Bs[lcol + 1][lrow + 64] = b1v.y;
        Bs[lcol + 2][lrow + 64] = b1v.z; Bs[lcol + 3][lrow + 64] = b1v.w;
        __syncthreads();

#pragma unroll
        for (int kk = 0; kk < 16; kk++) {
            float4 a0 = *(const float4*)&As[kk][ty * 4];
            float4 a1 = *(const float4*)&As[kk][64 + ty * 4];
            float4 b0 = *(const float4*)&Bs[kk][tx * 4];
            float4 b1 = *(const float4*)&Bs[kk][64 + tx * 4];
            float ar[8] = {a0.x, a0.y, a0.z, a0.w, a1.x, a1.y, a1.z, a1.w};
            float br[8] = {b0.x, b0.y, b0.z, b0.w, b1.x, b1.y, b1.z, b1.w};
#pragma unroll
            for (int i = 0; i < 8; i++)
#pragma unroll
                for (int j = 0; j < 8; j++)
                    acc[i][j] = fmaf(ar[i], br[j], acc[i][j]);
        }
        __syncthreads();
    }

#pragma unroll
    for (int jh = 0; jh < 2; jh++) {
        int c0 = blockIdx.x * 128 + jh * 64 + tx * 4;
        float4 bb = *(const float4*)(bias + c0);
#pragma unroll
        for (int ih = 0; ih < 2; ih++) {
#pragma unroll
            for (int i = 0; i < 4; i++) {
                int r = blockIdx.y * 128 + ih * 64 + ty * 4 + i;
                float4 v;
                v.x = acc[ih * 4 + i][jh * 4 + 0] + bb.x;
                v.y = acc[ih * 4 + i][jh * 4 + 1] + bb.y;
                v.z = acc[ih * 4 + i][jh * 4 + 2] + bb.z;
                v.w = acc[ih * 4 + i][jh * 4 + 3] + bb.w;
                if (relu) {
                    v.x = fmaxf(v.x, 0.f); v.y = fmaxf(v.y, 0.f);
                    v.z = fmaxf(v.z, 0.f); v.w = fmaxf(v.w, 0.f);
                }
                *(float4*)(C + (size_t)r * N + c0) = v;
            }
        }
    }
}

// ---------------------------------------------------------------------------
// Attention scores: for each (b,h): S = Q @ K^T / sqrt(D)
// Q,K strided views into qkv buffer (row stride 3E). 64x64 tiles, BK=16.
// ---------------------------------------------------------------------------
__global__ __launch_bounds__(256) void attn_scores(
    const float* __restrict__ qkv, float* __restrict__ sc)
{
    const int bh = blockIdx.z;
    const int b = bh >> 4, h = bh & 15;
    const float* Qb = qkv + (size_t)b * Tn * 3 * En + (size_t)h * Dn
                    + (size_t)blockIdx.y * 64 * 3 * En;
    const float* Kb = qkv + (size_t)b * Tn * 3 * En + En + (size_t)h * Dn
                    + (size_t)blockIdx.x * 64 * 3 * En;

    __shared__ float Qs[16][64];
    __shared__ float Ks[16][64];

    const int tid  = threadIdx.x;
    const int lrow = tid >> 2;        // 0..63
    const int lcol = (tid & 3) << 2;  // 0,4,8,12
    const int tx   = tid & 15;
    const int ty   = tid >> 4;

    float acc[4][4] = {};

    for (int k0 = 0; k0 < Dn; k0 += 16) {
        float4 q4 = *(const float4*)(Qb + (size_t)lrow * 3 * En + k0 + lcol);
        float4 k4 = *(const float4*)(Kb + (size_t)lrow * 3 * En + k0 + lcol);
        Qs[lcol + 0][lrow] = q4.x; Qs[lcol + 1][lrow] = q4.y;
        Qs[lcol + 2][lrow] = q4.z; Qs[lcol + 3][lrow] = q4.w;
        Ks[lcol + 0][lrow] = k4.x; Ks[lcol + 1][lrow] = k4.y;
        Ks[lcol + 2][lrow] = k4.z; Ks[lcol + 3][lrow] = k4.w;
        __syncthreads();
#pragma unroll
        for (int kk = 0; kk < 16; kk++) {
            float4 a = *(const float4*)&Qs[kk][ty * 4];
            float4 c = *(const float4*)&Ks[kk][tx * 4];
            float ar[4] = {a.x, a.y, a.z, a.w};
            float cr[4] = {c.x, c.y, c.z, c.w};
#pragma unroll
            for (int i = 0; i < 4; i++)
#pragma unroll
                for (int j = 0; j < 4; j++)
                    acc[i][j] = fmaf(ar[i], cr[j], acc[i][j]);
        }
        __syncthreads();
    }

    float* out = sc + (size_t)bh * Tn * Tn
               + (size_t)(blockIdx.y * 64 + ty * 4) * Tn
               + blockIdx.x * 64 + tx * 4;
#pragma unroll
    for (int i = 0; i < 4; i++) {
        float4 v = make_float4(acc[i][0] * 0.125f, acc[i][1] * 0.125f,
                               acc[i][2] * 0.125f, acc[i][3] * 0.125f);
        *(float4*)(out + (size_t)i * Tn) = v;
    }
}

// ---------------------------------------------------------------------------
// Fused softmax * gaussian * renorm over one score row of length T=512.
// final_k = p_k*gb_k / (sum_j p_j*gb_j + 1e-5 * sum_j p_j),  p = exp(s - max)
// ---------------------------------------------------------------------------
__global__ __launch_bounds__(256) void softmax_gauss(float* __restrict__ sc) {
    const int q = blockIdx.x & (Tn - 1);
    float* row = sc + (size_t)blockIdx.x * Tn;
    const int tid = threadIdx.x;

    float s0 = row[tid];
    float s1 = row[tid + 256];
    float m = blockReduceMax(fmaxf(s0, s1));

    float p0 = expf(s0 - m);
    float p1 = expf(s1 - m);
    float d0 = (float)(q - tid);
    float d1 = (float)(q - (tid + 256));
    float g0 = expf(-d0 * d0 * (1.0f / 32768.0f));
    float g1 = expf(-d1 * d1 * (1.0f / 32768.0f));

    float Z = blockReduceSum(p0 + p1);
    float G = blockReduceSum(p0 * g0 + p1 * g1);
    float inv = 1.0f / (G + 1e-5f * Z);

    row[tid]       = p0 * g0 * inv;
    row[tid + 256] = p1 * g1 * inv;
}

// ---------------------------------------------------------------------------
// Attention output: for each (b,h): O(512x64) = W(512x512) @ V(512x64)
// Writes into g_attn[b,t,h*64+d] (heads concatenated).
// ---------------------------------------------------------------------------
__global__ __launch_bounds__(256) void attn_o(
    const float* __restrict__ sc, const float* __restrict__ qkv,
    float* __restrict__ attn)
{
    const int bh = blockIdx.y;
    const int b = bh >> 4, h = bh & 15;
    const float* Wb = sc + (size_t)bh * Tn * Tn + (size_t)blockIdx.x * 64 * Tn;
    const float* Vb = qkv + (size_t)b * Tn * 3 * En + 2 * En + (size_t)h * Dn;

    __shared__ float Ws[32][64];  // [k][q]
    __shared__ float Vs[32][64];  // [k][d]

    const int tid = threadIdx.x;
    const int wr = tid >> 3;          // 0..31 (q rows, iterate +32)
    const int wc = (tid & 7) << 2;    // 0..28 (k cols)
    const int vr = tid >> 4;          // 0..15 (k rows, iterate +16)
    const int vc = (tid & 15) << 2;   // 0..60 (d cols)
    const int tx = tid & 15;
    const int ty = tid >> 4;

    float acc[4][4] = {};

    for (int k0 = 0; k0 < Tn; k0 += 32) {
        float4 w0 = *(const float4*)(Wb + (size_t)wr * Tn + k0 + wc);
        float4 w1 = *(const float4*)(Wb + (size_t)(wr + 32) * Tn + k0 + wc);
        float4 v0 = *(const float4*)(Vb + (size_t)(k0 + vr) * 3 * En + vc);
        float4 v1 = *(const float4*)(Vb + (size_t)(k0 + vr + 16) * 3 * En + vc);

        Ws[wc + 0][wr] = w0.x; Ws[wc + 1][wr] = w0.y;
        Ws[wc + 2][wr] = w0.z; Ws[wc + 3][wr] = w0.w;
        Ws[wc + 0][wr + 32] = w1.x; Ws[wc + 1][wr + 32] = w1.y;
        Ws[wc + 2][wr + 32] = w1.z; Ws[wc + 3][wr + 32] = w1.w;
        *(float4*)&Vs[vr][vc]      = v0;
        *(float4*)&Vs[vr + 16][vc] = v1;
        __syncthreads();

#pragma unroll
        for (int kk = 0; kk < 32; kk++) {
            float4 a = *(const float4*)&Ws[kk][ty * 4];
            float4 v = *(const float4*)&Vs[kk][tx * 4];
            float ar[4] = {a.x, a.y, a.z, a.w};
            float vrr[4] = {v.x, v.y, v.z, v.w};
#pragma unroll
            for (int i = 0; i < 4; i++)
#pragma unroll
                for (int j = 0; j < 4; j++)
                    acc[i][j] = fmaf(ar[i], vrr[j], acc[i][j]);
        }
        __syncthreads();
    }

    float* out = attn + (size_t)b * Tn * En
               + (size_t)(blockIdx.x * 64 + ty * 4) * En + h * Dn + tx * 4;
#pragma unroll
    for (int i = 0; i < 4; i++) {
        *(float4*)(out + (size_t)i * En) =
            make_float4(acc[i][0], acc[i][1], acc[i][2], acc[i][3]);
    }
}

// ---------------------------------------------------------------------------
// Residual add + LayerNorm, in place on x: x = LN(x + r) * g + b
// One block per row (E=1024), 256 threads x 4 elements.
// ---------------------------------------------------------------------------
__global__ __launch_bounds__(256) void add_ln(
    float* __restrict__ x, const float* __restrict__ r,
    const float* __restrict__ g, const float* __restrict__ bt)
{
    const size_t base = (size_t)blockIdx.x * En;
    const int tid = threadIdx.x;
    float v[4];
#pragma unroll
    for (int i = 0; i < 4; i++) {
        int c = tid + i * 256;
        v[i] = x[base + c] + r[base + c];
    }
    float mu = blockReduceSum(v[0] + v[1] + v[2] + v[3]) * (1.0f / En);
    float var = 0.f;
#pragma unroll
    for (int i = 0; i < 4; i++) { float d = v[i] - mu; var += d * d; }
    var = blockReduceSum(var) * (1.0f / En);
    float rs = rsqrtf(var + 1e-5f);
#pragma unroll
    for (int i = 0; i < 4; i++) {
        int c = tid + i * 256;
        x[base + c] = (v[i] - mu) * rs * g[c] + bt[c];
    }
}

// ---------------------------------------------------------------------------
// Head: out[b] = x[b, T-1, :] . head_w + head_b
// ---------------------------------------------------------------------------
__global__ __launch_bounds__(256) void head_kernel(
    const float* __restrict__ x, const float* __restrict__ hw,
    const float* __restrict__ hb, float* __restrict__ out)
{
    const int b = blockIdx.x;
    const int tid = threadIdx.x;
    const float* row = x + (size_t)b * Tn * En + (size_t)(Tn - 1) * En;
    float s = 0.f;
    for (int c = tid; c < En; c += 256) s += row[c] * hw[c];
    s = blockReduceSum(s);
    if (tid == 0) out[b] = s + hb[0];
}

// ---------------------------------------------------------------------------
// Launch
// ---------------------------------------------------------------------------
extern "C" void kernel_launch(void* const* d_in, const int* in_sizes, int n_in,
                              void* d_out, int out_size)
{
    const float* src    = (const float*)d_in[0];
    const float* in_w   = (const float*)d_in[1];
    const float* in_b   = (const float*)d_in[2];
    const float* outp_w = (const float*)d_in[3];
    const float* outp_b = (const float*)d_in[4];
    const float* ff1_w  = (const float*)d_in[5];
    const float* ff1_b  = (const float*)d_in[6];
    const float* ff2_w  = (const float*)d_in[7];
    const float* ff2_b  = (const float*)d_in[8];
    const float* ln1_g  = (const float*)d_in[9];
    const float* ln1_b  = (const float*)d_in[10];
    const float* ln2_g  = (const float*)d_in[11];
    const float* ln2_b  = (const float*)d_in[12];
    const float* head_w = (const float*)d_in[13];
    const float* head_b = (const float*)d_in[14];
    float* out = (float*)d_out;

    static float *x = nullptr, *qkv, *sc, *attn, *proj, *ff;
    if (!x) {
        cudaGetSymbolAddress((void**)&x,    g_x);
        cudaGetSymbolAddress((void**)&qkv,  g_qkv);
        cudaGetSymbolAddress((void**)&sc,   g_scores);
        cudaGetSymbolAddress((void**)&attn, g_attn);
        cudaGetSymbolAddress((void**)&proj, g_proj);
        cudaGetSymbolAddress((void**)&ff,   g_ff);
    }

    pe_add_kernel<<<Bn * Tn * En / 256, 256>>>(src, x);

    for (int l = 0; l < Ln; l++) {
        // qkv = x @ in_proj_w^T + in_proj_b        (4096 x 3072, K=1024)
        sgemm_nt<<<dim3(3 * En / 128, Bn * Tn / 128), 256>>>(
            x, in_w + (size_t)l * 3 * En * En, in_b + (size_t)l * 3 * En,
            qkv, Bn * Tn, 3 * En, En, 0);

        // scores = Q K^T / sqrt(D)
        attn_scores<<<dim3(Tn / 64, Tn / 64, Bn * Hn), 256>>>(qkv, sc);

        // softmax * gaussian, renormalized
        softmax_gauss<<<Bn * Hn * Tn, 256>>>(sc);

        // o = W V (heads concatenated into attn)
        attn_o<<<dim3(Tn / 64, Bn * Hn), 256>>>(sc, qkv, attn);

        // proj = attn @ out_w^T + out_b            (4096 x 1024, K=1024)
        sgemm_nt<<<dim3(En / 128, Bn * Tn / 128), 256>>>(
            attn, outp_w + (size_t)l * En * En, outp_b + (size_t)l * En,
            proj, Bn * Tn, En, En, 0);

        // x = LN1(x + proj)
        add_ln<<<Bn * Tn, 256>>>(x, proj, ln1_g + (size_t)l * En, ln1_b + (size_t)l * En);

        // ff = relu(x @ ff1_w^T + ff1_b)           (4096 x 4096, K=1024)
        sgemm_nt<<<dim3(FFn / 128, Bn * Tn / 128), 256>>>(
            x, ff1_w + (size_t)l * FFn * En, ff1_b + (size_t)l * FFn,
            ff, Bn * Tn, FFn, En, 1);

        // proj = ff @ ff2_w^T + ff2_b              (4096 x 1024, K=4096)
        sgemm_nt<<<dim3(En / 128, Bn * Tn / 128), 256>>>(
            ff, ff2_w + (size_t)l * En * FFn, ff2_b + (size_t)l * En,
            proj, Bn * Tn, En, FFn, 0);

        // x = LN2(x + proj)
        add_ln<<<Bn * Tn, 256>>>(x, proj, ln2_g + (size_t)l * En, ln2_b + (size_t)l * En);
    }

    head_kernel<<<Bn, 256>>>(x, head_w, head_b, out);
}

// round 5
// speedup vs baseline: 1.8907x; 1.8907x over previous
#include <cuda_runtime.h>
#include <cuda_bf16.h>
#include <math.h>
#include <stdint.h>

#define Bn  8
#define Tn  512
#define En  1024
#define Hn  16
#define Dn  64
#define Ln  4
#define FFn 4096

// fp32 scratch
__device__ float g_x[Bn * Tn * En];
__device__ float g_qkv[Bn * Tn * 3 * En];
__device__ float g_scores[Bn * Hn * Tn * Tn];
__device__ float g_proj[Bn * Tn * En];
// bf16 hi/lo activation pairs
__device__ __nv_bfloat16 g_xh[Bn * Tn * En],  g_xl[Bn * Tn * En];
__device__ __nv_bfloat16 g_ah[Bn * Tn * En],  g_al[Bn * Tn * En];
__device__ __nv_bfloat16 g_fh[Bn * Tn * FFn], g_fl[Bn * Tn * FFn];
// bf16 hi/lo weight pairs
__device__ __nv_bfloat16 g_wih[Ln * 3 * En * En], g_wil[Ln * 3 * En * En];
__device__ __nv_bfloat16 g_woh[Ln * En * En],     g_wol[Ln * En * En];
__device__ __nv_bfloat16 g_w1h[Ln * FFn * En],    g_w1l[Ln * FFn * En];
__device__ __nv_bfloat16 g_w2h[Ln * En * FFn],    g_w2l[Ln * En * FFn];

// ---------------- PTX helpers (all sm_80+, no tcgen05) ----------------
__device__ __forceinline__ uint32_t smem_u32(const void* p) {
    uint32_t a;
    asm("{ .reg .u64 t; cvta.to.shared.u64 t, %1; cvt.u32.u64 %0, t; }" : "=r"(a) : "l"(p));
    return a;
}
__device__ __forceinline__ void cpasync16(uint32_t dst, const void* src) {
    asm volatile("cp.async.cg.shared.global [%0], [%1], 16;" :: "r"(dst), "l"(src));
}
__device__ __forceinline__ void cp_commit() { asm volatile("cp.async.commit_group;" ::: "memory"); }
template <int N> __device__ __forceinline__ void cp_wait() {
    asm volatile("cp.async.wait_group %0;" :: "n"(N) : "memory");
}
__device__ __forceinline__ void ldsm4(uint32_t& r0, uint32_t& r1, uint32_t& r2,
                                      uint32_t& r3, uint32_t a) {
    asm volatile("ldmatrix.sync.aligned.m8n8.x4.shared.b16 {%0,%1,%2,%3}, [%4];"
                 : "=r"(r0), "=r"(r1), "=r"(r2), "=r"(r3) : "r"(a));
}
__device__ __forceinline__ void mma16816(float* d, const uint32_t* a, uint32_t b0, uint32_t b1) {
    asm volatile("mma.sync.aligned.m16n8k16.row.col.f32.bf16.bf16.f32 "
                 "{%0,%1,%2,%3}, {%4,%5,%6,%7}, {%8,%9}, {%0,%1,%2,%3};"
                 : "+f"(d[0]), "+f"(d[1]), "+f"(d[2]), "+f"(d[3])
                 : "r"(a[0]), "r"(a[1]), "r"(a[2]), "r"(a[3]), "r"(b0), "r"(b1));
}
__device__ __forceinline__ void split_hl(float v, __nv_bfloat16& h, __nv_bfloat16& l) {
    h = __float2bfloat16(v);
    l = __float2bfloat16(v - __bfloat162float(h));
}

// ---------------- reductions ----------------
__device__ __forceinline__ float warpSum(float v) {
#pragma unroll
    for (int o = 16; o; o >>= 1) v += __shfl_xor_sync(~0u, v, o);
    return v;
}
__device__ __forceinline__ float warpMax(float v) {
#pragma unroll
    for (int o = 16; o; o >>= 1) v = fmaxf(v, __shfl_xor_sync(~0u, v, o));
    return v;
}
__device__ __forceinline__ float blockSum(float v) {
    __shared__ float sm[8];
    int lane = threadIdx.x & 31, wid = threadIdx.x >> 5;
    v = warpSum(v);
    __syncthreads();
    if (lane == 0) sm[wid] = v;
    __syncthreads();
    v = sm[lane & 7];
#pragma unroll
    for (int o = 4; o; o >>= 1) v += __shfl_xor_sync(~0u, v, o);
    return v;
}
__device__ __forceinline__ float blockMax(float v) {
    __shared__ float sm[8];
    int lane = threadIdx.x & 31, wid = threadIdx.x >> 5;
    v = warpMax(v);
    __syncthreads();
    if (lane == 0) sm[wid] = v;
    __syncthreads();
    v = sm[lane & 7];
#pragma unroll
    for (int o = 4; o; o >>= 1) v = fmaxf(v, __shfl_xor_sync(~0u, v, o));
    return v;
}

// ---------------- small kernels ----------------
__global__ void convert_hl(const float* __restrict__ s, __nv_bfloat16* __restrict__ h,
                           __nv_bfloat16* __restrict__ l) {
    int i = blockIdx.x * 256 + threadIdx.x;
    split_hl(s[i], h[i], l[i]);
}

__global__ void pe_add_kernel(const float* __restrict__ src, float* __restrict__ x,
                              __nv_bfloat16* __restrict__ xh, __nv_bfloat16* __restrict__ xl) {
    int idx = blockIdx.x * 256 + threadIdx.x;
    int e = idx & (En - 1);
    int b = idx / (Tn * En);
    float dv = expf((float)(e & ~1) * (-9.210340371976184f / (float)En));
    float ang = (float)b * dv;
    float pe = (e & 1) ? cosf(ang) : sinf(ang);
    float v = src[idx] + pe;
    x[idx] = v;
    split_hl(v, xh[idx], xl[idx]);
}

// ---------------- mma.sync bf16 GEMM with hi/lo 3-segment split ----------------
// C[4096, N] = (Ah+Al)[4096,K] @ (Bh+Bl)[N,K]^T + bias  (AlBl dropped, ~2^-16)
// CTA 128x128, BK=32, 4-stage cp.async, warp tile 32x64.
// Smem rows are 64B (32 bf16). Swizzle: 16B chunk c at row r -> c ^ ((r>>1)&3).
#define BM 128
#define BN 128
#define BK 32
#define STGB (BM * 64 + BN * 64)   // 16 KB per stage

__global__ __launch_bounds__(256, 2) void gemm_mma(
    const __nv_bfloat16* __restrict__ Ah, const __nv_bfloat16* __restrict__ Al,
    const __nv_bfloat16* __restrict__ Bh, const __nv_bfloat16* __restrict__ Bl,
    const float* __restrict__ bias, float* __restrict__ Cf,
    __nv_bfloat16* __restrict__ Ch, __nv_bfloat16* __restrict__ Cl,
    int K, int N, int relu)
{
    extern __shared__ __align__(128) uint8_t dsm[];
    __shared__ float sh_bias[BN];

    const int tid = threadIdx.x;
    const uint32_t sbase = smem_u32(dsm);
    if (tid < BN) sh_bias[tid] = bias[blockIdx.x * BN + tid];

    const int wid = tid >> 5, lane = tid & 31;
    const int wm = wid >> 1, wn = wid & 1;   // 4 x 2 warp grid

    const int cps = K / BK;
    const int C = 3 * cps;

    auto load_chunk = [&](int c, int st) {
        int seg = (c >= cps) + (c >= 2 * cps);
        int kc = (c - seg * cps) * BK;
        const __nv_bfloat16* Ap = (seg == 1 ? Al : Ah) + (size_t)blockIdx.y * BM * K + kc;
        const __nv_bfloat16* Bp = (seg == 2 ? Bl : Bh) + (size_t)blockIdx.x * BN * K + kc;
        uint32_t sA = sbase + (uint32_t)st * STGB;
        uint32_t sB = sA + BM * 64;
#pragma unroll
        for (int j = 0; j < 2; j++) {
            int idx = tid + j * 256;
            int r = idx >> 2, cc = idx & 3;
            uint32_t off = r * 64 + ((cc ^ ((r >> 1) & 3)) << 4);
            cpasync16(sA + off, Ap + (size_t)r * K + cc * 8);
        }
#pragma unroll
        for (int j = 0; j < 2; j++) {
            int idx = tid + j * 256;
            int r = idx >> 2, cc = idx & 3;
            uint32_t off = r * 64 + ((cc ^ ((r >> 1) & 3)) << 4);
            cpasync16(sB + off, Bp + (size_t)r * K + cc * 8);
        }
        cp_commit();
    };

    float acc[2][8][4] = {};

    load_chunk(0, 0);
    load_chunk(1, 1);
    load_chunk(2, 2);

    for (int c = 0; c < C; c++) {
        if (c < C - 2)      cp_wait<2>();
        else if (c == C - 2) cp_wait<1>();
        else                 cp_wait<0>();
        __syncthreads();
        if (c + 3 < C) load_chunk(c + 3, (c + 3) & 3);

        uint32_t sA = sbase + (uint32_t)(c & 3) * STGB;
        uint32_t sB = sA + BM * 64;
#pragma unroll
        for (int ks = 0; ks < 2; ks++) {
            uint32_t af[2][4];
#pragma unroll
            for (int ti = 0; ti < 2; ti++) {
                int r = wm * 32 + ti * 16 + (lane & 15);
                int cc = 2 * ks + (lane >> 4);
                ldsm4(af[ti][0], af[ti][1], af[ti][2], af[ti][3],
                      sA + r * 64 + ((cc ^ ((r >> 1) & 3)) << 4));
            }
#pragma unroll
            for (int tj = 0; tj < 4; tj++) {
                uint32_t b0, b1, b2, b3;
                int r = wn * 64 + tj * 16 + (lane & 15);
                int cc = 2 * ks + (lane >> 4);
                ldsm4(b0, b1, b2, b3, sB + r * 64 + ((cc ^ ((r >> 1) & 3)) << 4));
                // n8 tile (2tj): {b0,b2} ; tile (2tj+1): {b1,b3}
                mma16816(acc[0][2 * tj],     af[0], b0, b2);
                mma16816(acc[0][2 * tj + 1], af[0], b1, b3);
                mma16816(acc[1][2 * tj],     af[1], b0, b2);
                mma16816(acc[1][2 * tj + 1], af[1], b1, b3);
            }
        }
    }

    // epilogue
    const int col0 = wn * 64;
    const int row0 = blockIdx.y * BM + wm * 32;
#pragma unroll
    for (int ti = 0; ti < 2; ti++) {
#pragma unroll
        for (int tj = 0; tj < 8; tj++) {
            int cl = col0 + tj * 8 + 2 * (lane & 3);
            int colg = blockIdx.x * BN + cl;
            float b0 = sh_bias[cl], b1 = sh_bias[cl + 1];
#pragma unroll
            for (int hh = 0; hh < 2; hh++) {
                int row = row0 + ti * 16 + (lane >> 2) + hh * 8;
                float v0 = acc[ti][tj][2 * hh + 0] + b0;
                float v1 = acc[ti][tj][2 * hh + 1] + b1;
                if (relu) { v0 = fmaxf(v0, 0.f); v1 = fmaxf(v1, 0.f); }
                size_t o = (size_t)row * N + colg;
                if (Cf) *(float2*)(Cf + o) = make_float2(v0, v1);
                if (Ch) {
                    __nv_bfloat16 h0, l0, h1, l1;
                    split_hl(v0, h0, l0);
                    split_hl(v1, h1, l1);
                    __nv_bfloat162 hv; hv.x = h0; hv.y = h1;
                    __nv_bfloat162 lv; lv.x = l0; lv.y = l1;
                    *(__nv_bfloat162*)(Ch + o) = hv;
                    *(__nv_bfloat162*)(Cl + o) = lv;
                }
            }
        }
    }
}

// ---------------- attention (fp32, proven in R1) ----------------
__global__ __launch_bounds__(256) void attn_scores(
    const float* __restrict__ qkv, float* __restrict__ sc)
{
    const int bh = blockIdx.z;
    const int b = bh >> 4, h = bh & 15;
    const float* Qb = qkv + (size_t)b * Tn * 3 * En + (size_t)h * Dn + (size_t)blockIdx.y * 64 * 3 * En;
    const float* Kb = qkv + (size_t)b * Tn * 3 * En + En + (size_t)h * Dn + (size_t)blockIdx.x * 64 * 3 * En;
    __shared__ float Qs[16][64];
    __shared__ float Ks[16][64];
    const int tid = threadIdx.x;
    const int lrow = tid >> 2, lcol = (tid & 3) << 2;
    const int tx = tid & 15, ty = tid >> 4;
    float acc[4][4] = {};
    for (int k0 = 0; k0 < Dn; k0 += 16) {
        float4 q4 = *(const float4*)(Qb + (size_t)lrow * 3 * En + k0 + lcol);
        float4 k4 = *(const float4*)(Kb + (size_t)lrow * 3 * En + k0 + lcol);
        Qs[lcol+0][lrow]=q4.x; Qs[lcol+1][lrow]=q4.y; Qs[lcol+2][lrow]=q4.z; Qs[lcol+3][lrow]=q4.w;
        Ks[lcol+0][lrow]=k4.x; Ks[lcol+1][lrow]=k4.y; Ks[lcol+2][lrow]=k4.z; Ks[lcol+3][lrow]=k4.w;
        __syncthreads();
#pragma unroll
        for (int kk = 0; kk < 16; kk++) {
            float4 a = *(const float4*)&Qs[kk][ty*4];
            float4 c = *(const float4*)&Ks[kk][tx*4];
            float ar[4] = {a.x,a.y,a.z,a.w}, cr[4] = {c.x,c.y,c.z,c.w};
#pragma unroll
            for (int i = 0; i < 4; i++)
#pragma unroll
                for (int j = 0; j < 4; j++) acc[i][j] = fmaf(ar[i], cr[j], acc[i][j]);
        }
        __syncthreads();
    }
    float* out = sc + (size_t)bh*Tn*Tn + (size_t)(blockIdx.y*64 + ty*4)*Tn + blockIdx.x*64 + tx*4;
#pragma unroll
    for (int i = 0; i < 4; i++)
        *(float4*)(out + (size_t)i*Tn) = make_float4(acc[i][0]*0.125f, acc[i][1]*0.125f,
                                                     acc[i][2]*0.125f, acc[i][3]*0.125f);
}

__global__ __launch_bounds__(256) void softmax_gauss(float* __restrict__ sc) {
    const int q = blockIdx.x & (Tn - 1);
    float* row = sc + (size_t)blockIdx.x * Tn;
    const int tid = threadIdx.x;
    float s0 = row[tid], s1 = row[tid + 256];
    float m = blockMax(fmaxf(s0, s1));
    float p0 = expf(s0 - m), p1 = expf(s1 - m);
    float d0 = (float)(q - tid), d1 = (float)(q - (tid + 256));
    float g0 = expf(-d0 * d0 * (1.0f / 32768.0f));
    float g1 = expf(-d1 * d1 * (1.0f / 32768.0f));
    float Z = blockSum(p0 + p1);
    float G = blockSum(p0 * g0 + p1 * g1);
    float inv = 1.0f / (G + 1e-5f * Z);
    row[tid] = p0 * g0 * inv;
    row[tid + 256] = p1 * g1 * inv;
}

__global__ __launch_bounds__(256) void attn_o(
    const float* __restrict__ sc, const float* __restrict__ qkv,
    __nv_bfloat16* __restrict__ oh, __nv_bfloat16* __restrict__ ol)
{
    const int bh = blockIdx.y;
    const int b = bh >> 4, h = bh & 15;
    const float* Wb = sc + (size_t)bh * Tn * Tn + (size_t)blockIdx.x * 64 * Tn;
    const float* Vb = qkv + (size_t)b * Tn * 3 * En + 2 * En + (size_t)h * Dn;
    __shared__ float Ws[32][64];
    __shared__ float Vs[32][64];
    const int tid = threadIdx.x;
    const int wr = tid >> 3, wc = (tid & 7) << 2;
    const int vr = tid >> 4, vc = (tid & 15) << 2;
    const int tx = tid & 15, ty = tid >> 4;
    float acc[4][4] = {};
    for (int k0 = 0; k0 < Tn; k0 += 32) {
        float4 w0 = *(const float4*)(Wb + (size_t)wr * Tn + k0 + wc);
        float4 w1 = *(const float4*)(Wb + (size_t)(wr + 32) * Tn + k0 + wc);
        float4 v0 = *(const float4*)(Vb + (size_t)(k0 + vr) * 3 * En + vc);
        float4 v1 = *(const float4*)(Vb + (size_t)(k0 + vr + 16) * 3 * En + vc);
        Ws[wc+0][wr]=w0.x; Ws[wc+1][wr]=w0.y; Ws[wc+2][wr]=w0.z; Ws[wc+3][wr]=w0.w;
        Ws[wc+0][wr+32]=w1.x; Ws[wc+1][wr+32]=w1.y; Ws[wc+2][wr+32]=w1.z; Ws[wc+3][wr+32]=w1.w;
        *(float4*)&Vs[vr][vc] = v0;
        *(float4*)&Vs[vr+16][vc] = v1;
        __syncthreads();
#pragma unroll
        for (int kk = 0; kk < 32; kk++) {
            float4 a = *(const float4*)&Ws[kk][ty*4];
            float4 v = *(const float4*)&Vs[kk][tx*4];
            float ar[4] = {a.x,a.y,a.z,a.w}, vv[4] = {v.x,v.y,v.z,v.w};
#pragma unroll
            for (int i = 0; i < 4; i++)
#pragma unroll
                for (int j = 0; j < 4; j++) acc[i][j] = fmaf(ar[i], vv[j], acc[i][j]);
        }
        __syncthreads();
    }
    size_t base = (size_t)b*Tn*En + (size_t)(blockIdx.x*64 + ty*4)*En + h*Dn + tx*4;
#pragma unroll
    for (int i = 0; i < 4; i++) {
#pragma unroll
        for (int j = 0; j < 4; j += 2) {
            __nv_bfloat16 h0, l0, h1, l1;
            split_hl(acc[i][j], h0, l0);
            split_hl(acc[i][j+1], h1, l1);
            __nv_bfloat162 hv; hv.x = h0; hv.y = h1;
            __nv_bfloat162 lv; lv.x = l0; lv.y = l1;
            *(__nv_bfloat162*)(oh + base + (size_t)i*En + j) = hv;
            *(__nv_bfloat162*)(ol + base + (size_t)i*En + j) = lv;
        }
    }
}

__global__ __launch_bounds__(256) void add_ln(
    float* __restrict__ x, const float* __restrict__ r,
    const float* __restrict__ g, const float* __restrict__ bt,
    __nv_bfloat16* __restrict__ xh, __nv_bfloat16* __restrict__ xl)
{
    const size_t base = (size_t)blockIdx.x * En;
    const int tid = threadIdx.x;
    float v[4];
#pragma unroll
    for (int i = 0; i < 4; i++) { int c = tid + i*256; v[i] = x[base+c] + r[base+c]; }
    float mu = blockSum(v[0]+v[1]+v[2]+v[3]) * (1.0f/En);
    float var = 0.f;
#pragma unroll
    for (int i = 0; i < 4; i++) { float d = v[i]-mu; var += d*d; }
    var = blockSum(var) * (1.0f/En);
    float rs = rsqrtf(var + 1e-5f);
#pragma unroll
    for (int i = 0; i < 4; i++) {
        int c = tid + i*256;
        float o = (v[i]-mu)*rs*g[c] + bt[c];
        x[base+c] = o;
        split_hl(o, xh[base+c], xl[base+c]);
    }
}

__global__ __launch_bounds__(256) void head_kernel(
    const float* __restrict__ x, const float* __restrict__ hw,
    const float* __restrict__ hb, float* __restrict__ out)
{
    const int b = blockIdx.x;
    const int tid = threadIdx.x;
    const float* row = x + (size_t)b*Tn*En + (size_t)(Tn-1)*En;
    float s = 0.f;
    for (int c = tid; c < En; c += 256) s += row[c] * hw[c];
    s = blockSum(s);
    if (tid == 0) out[b] = s + hb[0];
}

// ---------------- launch ----------------
extern "C" void kernel_launch(void* const* d_in, const int* in_sizes, int n_in,
                              void* d_out, int out_size)
{
    const float* src    = (const float*)d_in[0];
    const float* in_w   = (const float*)d_in[1];
    const float* in_b   = (const float*)d_in[2];
    const float* outp_w = (const float*)d_in[3];
    const float* outp_b = (const float*)d_in[4];
    const float* ff1_w  = (const float*)d_in[5];
    const float* ff1_b  = (const float*)d_in[6];
    const float* ff2_w  = (const float*)d_in[7];
    const float* ff2_b  = (const float*)d_in[8];
    const float* ln1_g  = (const float*)d_in[9];
    const float* ln1_b  = (const float*)d_in[10];
    const float* ln2_g  = (const float*)d_in[11];
    const float* ln2_b  = (const float*)d_in[12];
    const float* head_w = (const float*)d_in[13];
    const float* head_b = (const float*)d_in[14];
    float* out = (float*)d_out;

    static bool init = false;
    static float *x, *qkv, *sc, *proj;
    static __nv_bfloat16 *xh,*xl,*ah,*al,*fh,*fl,*wih,*wil,*woh,*wol,*w1h,*w1l,*w2h,*w2l;
    if (!init) {
        cudaGetSymbolAddress((void**)&x, g_x);   cudaGetSymbolAddress((void**)&qkv, g_qkv);
        cudaGetSymbolAddress((void**)&sc, g_scores); cudaGetSymbolAddress((void**)&proj, g_proj);
        cudaGetSymbolAddress((void**)&xh, g_xh); cudaGetSymbolAddress((void**)&xl, g_xl);
        cudaGetSymbolAddress((void**)&ah, g_ah); cudaGetSymbolAddress((void**)&al, g_al);
        cudaGetSymbolAddress((void**)&fh, g_fh); cudaGetSymbolAddress((void**)&fl, g_fl);
        cudaGetSymbolAddress((void**)&wih, g_wih); cudaGetSymbolAddress((void**)&wil, g_wil);
        cudaGetSymbolAddress((void**)&woh, g_woh); cudaGetSymbolAddress((void**)&wol, g_wol);
        cudaGetSymbolAddress((void**)&w1h, g_w1h); cudaGetSymbolAddress((void**)&w1l, g_w1l);
        cudaGetSymbolAddress((void**)&w2h, g_w2h); cudaGetSymbolAddress((void**)&w2l, g_w2l);
        cudaFuncSetAttribute(gemm_mma, cudaFuncAttributeMaxDynamicSharedMemorySize, 4 * STGB);
        init = true;
    }

    // weight -> hi/lo bf16 (cheap, graph-captured)
    convert_hl<<<Ln * 3 * En * En / 256, 256>>>(in_w, wih, wil);
    convert_hl<<<Ln * En * En / 256, 256>>>(outp_w, woh, wol);
    convert_hl<<<Ln * FFn * En / 256, 256>>>(ff1_w, w1h, w1l);
    convert_hl<<<Ln * En * FFn / 256, 256>>>(ff2_w, w2h, w2l);

    pe_add_kernel<<<Bn * Tn * En / 256, 256>>>(src, x, xh, xl);

    for (int l = 0; l < Ln; l++) {
        size_t wo3 = (size_t)l * 3 * En * En, wo1 = (size_t)l * En * En;
        size_t wof = (size_t)l * FFn * En;
        // qkv = x @ in_proj^T + b                        (4096 x 3072, K=1024)
        gemm_mma<<<dim3(3 * En / BN, Bn * Tn / BM), 256, 4 * STGB>>>(
            xh, xl, wih + wo3, wil + wo3, in_b + (size_t)l * 3 * En,
            qkv, nullptr, nullptr, En, 3 * En, 0);
        attn_scores<<<dim3(Tn / 64, Tn / 64, Bn * Hn), 256>>>(qkv, sc);
        softmax_gauss<<<Bn * Hn * Tn, 256>>>(sc);
        attn_o<<<dim3(Tn / 64, Bn * Hn), 256>>>(sc, qkv, ah, al);
        // proj = attn @ out_w^T + b                      (4096 x 1024, K=1024)
        gemm_mma<<<dim3(En / BN, Bn * Tn / BM), 256, 4 * STGB>>>(
            ah, al, woh + wo1, wol + wo1, outp_b + (size_t)l * En,
            proj, nullptr, nullptr, En, En, 0);
        add_ln<<<Bn * Tn, 256>>>(x, proj, ln1_g + (size_t)l * En, ln1_b + (size_t)l * En, xh, xl);
        // ff = relu(x @ ff1^T + b)  (hl out only)        (4096 x 4096, K=1024)
        gemm_mma<<<dim3(FFn / BN, Bn * Tn / BM), 256, 4 * STGB>>>(
            xh, xl, w1h + wof, w1l + wof, ff1_b + (size_t)l * FFn,
            nullptr, fh, fl, En, FFn, 1);
        // proj = ff @ ff2^T + b                          (4096 x 1024, K=4096)
        gemm_mma<<<dim3(En / BN, Bn * Tn / BM), 256, 4 * STGB>>>(
            fh, fl, w2h + wof, w2l + wof, ff2_b + (size_t)l * En,
            proj, nullptr, nullptr, FFn, En, 0);
        add_ln<<<Bn * Tn, 256>>>(x, proj, ln2_g + (size_t)l * En, ln2_b + (size_t)l * En, xh, xl);
    }

    head_kernel<<<Bn, 256>>>(x, head_w, head_b, out);
}

// round 6
// speedup vs baseline: 2.1089x; 1.1154x over previous
#include <cuda_runtime.h>
#include <cuda_bf16.h>
#include <math.h>
#include <stdint.h>

#define Bn  8
#define Tn  512
#define En  1024
#define Hn  16
#define Dn  64
#define Ln  4
#define FFn 4096

// fp32 scratch
__device__ float g_x[Bn * Tn * En];
__device__ float g_scores[Bn * Hn * Tn * Tn];
__device__ float g_proj[Bn * Tn * En];
// bf16 hi/lo activation pairs
__device__ __nv_bfloat16 g_xh[Bn * Tn * En],  g_xl[Bn * Tn * En];
__device__ __nv_bfloat16 g_ah[Bn * Tn * En],  g_al[Bn * Tn * En];
__device__ __nv_bfloat16 g_fh[Bn * Tn * FFn], g_fl[Bn * Tn * FFn];
__device__ __nv_bfloat16 g_qkvh[Bn * Tn * 3 * En], g_qkvl[Bn * Tn * 3 * En];
__device__ __nv_bfloat16 g_wprh[Bn * Hn * Tn * Tn], g_wprl[Bn * Hn * Tn * Tn];
// bf16 hi/lo weight pairs
__device__ __nv_bfloat16 g_wih[Ln * 3 * En * En], g_wil[Ln * 3 * En * En];
__device__ __nv_bfloat16 g_woh[Ln * En * En],     g_wol[Ln * En * En];
__device__ __nv_bfloat16 g_w1h[Ln * FFn * En],    g_w1l[Ln * FFn * En];
__device__ __nv_bfloat16 g_w2h[Ln * En * FFn],    g_w2l[Ln * En * FFn];

// ---------------- PTX helpers (sm_80+ only) ----------------
__device__ __forceinline__ uint32_t smem_u32(const void* p) {
    uint32_t a;
    asm("{ .reg .u64 t; cvta.to.shared.u64 t, %1; cvt.u32.u64 %0, t; }" : "=r"(a) : "l"(p));
    return a;
}
__device__ __forceinline__ void cpasync16(uint32_t dst, const void* src) {
    asm volatile("cp.async.cg.shared.global [%0], [%1], 16;" :: "r"(dst), "l"(src));
}
__device__ __forceinline__ void cp_commit() { asm volatile("cp.async.commit_group;" ::: "memory"); }
template <int N> __device__ __forceinline__ void cp_wait() {
    asm volatile("cp.async.wait_group %0;" :: "n"(N) : "memory");
}
__device__ __forceinline__ void ldsm4(uint32_t& r0, uint32_t& r1, uint32_t& r2,
                                      uint32_t& r3, uint32_t a) {
    asm volatile("ldmatrix.sync.aligned.m8n8.x4.shared.b16 {%0,%1,%2,%3}, [%4];"
                 : "=r"(r0), "=r"(r1), "=r"(r2), "=r"(r3) : "r"(a));
}
__device__ __forceinline__ void mma16816(float* d, const uint32_t* a, uint32_t b0, uint32_t b1) {
    asm volatile("mma.sync.aligned.m16n8k16.row.col.f32.bf16.bf16.f32 "
                 "{%0,%1,%2,%3}, {%4,%5,%6,%7}, {%8,%9}, {%0,%1,%2,%3};"
                 : "+f"(d[0]), "+f"(d[1]), "+f"(d[2]), "+f"(d[3])
                 : "r"(a[0]), "r"(a[1]), "r"(a[2]), "r"(a[3]), "r"(b0), "r"(b1));
}
__device__ __forceinline__ void split_hl(float v, __nv_bfloat16& h, __nv_bfloat16& l) {
    h = __float2bfloat16(v);
    l = __float2bfloat16(v - __bfloat162float(h));
}

// ---------------- reductions ----------------
__device__ __forceinline__ float warpSum(float v) {
#pragma unroll
    for (int o = 16; o; o >>= 1) v += __shfl_xor_sync(~0u, v, o);
    return v;
}
__device__ __forceinline__ float warpMax(float v) {
#pragma unroll
    for (int o = 16; o; o >>= 1) v = fmaxf(v, __shfl_xor_sync(~0u, v, o));
    return v;
}
__device__ __forceinline__ float blockSum(float v) {
    __shared__ float sm[8];
    int lane = threadIdx.x & 31, wid = threadIdx.x >> 5;
    v = warpSum(v);
    __syncthreads();
    if (lane == 0) sm[wid] = v;
    __syncthreads();
    v = sm[lane & 7];
#pragma unroll
    for (int o = 4; o; o >>= 1) v += __shfl_xor_sync(~0u, v, o);
    return v;
}
__device__ __forceinline__ float blockMax(float v) {
    __shared__ float sm[8];
    int lane = threadIdx.x & 31, wid = threadIdx.x >> 5;
    v = warpMax(v);
    __syncthreads();
    if (lane == 0) sm[wid] = v;
    __syncthreads();
    v = sm[lane & 7];
#pragma unroll
    for (int o = 4; o; o >>= 1) v = fmaxf(v, __shfl_xor_sync(~0u, v, o));
    return v;
}

// ---------------- small kernels ----------------
__global__ void convert_hl4(const float4* __restrict__ s,
                            __nv_bfloat162* __restrict__ h,
                            __nv_bfloat162* __restrict__ l) {
    int i = blockIdx.x * 256 + threadIdx.x;
    float4 v = s[i];
    __nv_bfloat16 h0,l0,h1,l1,h2,l2,h3,l3;
    split_hl(v.x, h0, l0); split_hl(v.y, h1, l1);
    split_hl(v.z, h2, l2); split_hl(v.w, h3, l3);
    __nv_bfloat162 a, b, c, d;
    a.x = h0; a.y = h1; b.x = h2; b.y = h3;
    c.x = l0; c.y = l1; d.x = l2; d.y = l3;
    h[2*i] = a; h[2*i+1] = b;
    l[2*i] = c; l[2*i+1] = d;
}

__global__ void pe_add_kernel(const float* __restrict__ src, float* __restrict__ x,
                              __nv_bfloat16* __restrict__ xh, __nv_bfloat16* __restrict__ xl) {
    int idx = blockIdx.x * 256 + threadIdx.x;
    int e = idx & (En - 1);
    int b = idx / (Tn * En);
    float dv = expf((float)(e & ~1) * (-9.210340371976184f / (float)En));
    float ang = (float)b * dv;
    float pe = (e & 1) ? cosf(ang) : sinf(ang);
    float v = src[idx] + pe;
    x[idx] = v;
    split_hl(v, xh[idx], xl[idx]);
}

// ---------------- mma.sync bf16 GEMM with hi/lo 3-segment split ----------------
#define BM 128
#define BN 128
#define BK 32
#define STGB (BM * 64 + BN * 64)   // 16 KB per stage

__global__ __launch_bounds__(256, 2) void gemm_mma(
    const __nv_bfloat16* __restrict__ Ah, const __nv_bfloat16* __restrict__ Al,
    const __nv_bfloat16* __restrict__ Bh, const __nv_bfloat16* __restrict__ Bl,
    const float* __restrict__ bias, float* __restrict__ Cf,
    __nv_bfloat16* __restrict__ Ch, __nv_bfloat16* __restrict__ Cl,
    int K, int N, int relu)
{
    extern __shared__ __align__(128) uint8_t dsm[];
    __shared__ float sh_bias[BN];

    const int tid = threadIdx.x;
    const uint32_t sbase = smem_u32(dsm);
    if (tid < BN) sh_bias[tid] = bias[blockIdx.x * BN + tid];

    const int wid = tid >> 5, lane = tid & 31;
    const int wm = wid >> 1, wn = wid & 1;

    const int cps = K / BK;
    const int C = 3 * cps;

    auto load_chunk = [&](int c, int st) {
        int seg = (c >= cps) + (c >= 2 * cps);
        int kc = (c - seg * cps) * BK;
        const __nv_bfloat16* Ap = (seg == 1 ? Al : Ah) + (size_t)blockIdx.y * BM * K + kc;
        const __nv_bfloat16* Bp = (seg == 2 ? Bl : Bh) + (size_t)blockIdx.x * BN * K + kc;
        uint32_t sA = sbase + (uint32_t)st * STGB;
        uint32_t sB = sA + BM * 64;
#pragma unroll
        for (int j = 0; j < 2; j++) {
            int idx = tid + j * 256;
            int r = idx >> 2, cc = idx & 3;
            uint32_t off = r * 64 + ((cc ^ ((r >> 1) & 3)) << 4);
            cpasync16(sA + off, Ap + (size_t)r * K + cc * 8);
        }
#pragma unroll
        for (int j = 0; j < 2; j++) {
            int idx = tid + j * 256;
            int r = idx >> 2, cc = idx & 3;
            uint32_t off = r * 64 + ((cc ^ ((r >> 1) & 3)) << 4);
            cpasync16(sB + off, Bp + (size_t)r * K + cc * 8);
        }
        cp_commit();
    };

    float acc[2][8][4] = {};
    load_chunk(0, 0);
    load_chunk(1, 1);
    load_chunk(2, 2);

    for (int c = 0; c < C; c++) {
        if (c < C - 2)      cp_wait<2>();
        else if (c == C - 2) cp_wait<1>();
        else                 cp_wait<0>();
        __syncthreads();
        if (c + 3 < C) load_chunk(c + 3, (c + 3) & 3);

        uint32_t sA = sbase + (uint32_t)(c & 3) * STGB;
        uint32_t sB = sA + BM * 64;
#pragma unroll
        for (int ks = 0; ks < 2; ks++) {
            uint32_t af[2][4];
#pragma unroll
            for (int ti = 0; ti < 2; ti++) {
                int r = wm * 32 + ti * 16 + (lane & 15);
                int cc = 2 * ks + (lane >> 4);
                ldsm4(af[ti][0], af[ti][1], af[ti][2], af[ti][3],
                      sA + r * 64 + ((cc ^ ((r >> 1) & 3)) << 4));
            }
#pragma unroll
            for (int tj = 0; tj < 4; tj++) {
                uint32_t b0, b1, b2, b3;
                int r = wn * 64 + tj * 16 + (lane & 15);
                int cc = 2 * ks + (lane >> 4);
                ldsm4(b0, b1, b2, b3, sB + r * 64 + ((cc ^ ((r >> 1) & 3)) << 4));
                mma16816(acc[0][2 * tj],     af[0], b0, b2);
                mma16816(acc[0][2 * tj + 1], af[0], b1, b3);
                mma16816(acc[1][2 * tj],     af[1], b0, b2);
                mma16816(acc[1][2 * tj + 1], af[1], b1, b3);
            }
        }
    }

    const int col0 = wn * 64;
    const int row0 = blockIdx.y * BM + wm * 32;
#pragma unroll
    for (int ti = 0; ti < 2; ti++) {
#pragma unroll
        for (int tj = 0; tj < 8; tj++) {
            int cl = col0 + tj * 8 + 2 * (lane & 3);
            int colg = blockIdx.x * BN + cl;
            float b0 = sh_bias[cl], b1 = sh_bias[cl + 1];
#pragma unroll
            for (int hh = 0; hh < 2; hh++) {
                int row = row0 + ti * 16 + (lane >> 2) + hh * 8;
                float v0 = acc[ti][tj][2 * hh + 0] + b0;
                float v1 = acc[ti][tj][2 * hh + 1] + b1;
                if (relu) { v0 = fmaxf(v0, 0.f); v1 = fmaxf(v1, 0.f); }
                size_t o = (size_t)row * N + colg;
                if (Cf) *(float2*)(Cf + o) = make_float2(v0, v1);
                if (Ch) {
                    __nv_bfloat16 h0, l0, h1, l1;
                    split_hl(v0, h0, l0);
                    split_hl(v1, h1, l1);
                    __nv_bfloat162 hv; hv.x = h0; hv.y = h1;
                    __nv_bfloat162 lv; lv.x = l0; lv.y = l1;
                    *(__nv_bfloat162*)(Ch + o) = hv;
                    *(__nv_bfloat162*)(Cl + o) = lv;
                }
            }
        }
    }
}

// ---------------- scores: S = Q K^T / 8 on tensor cores (NT, hi/lo) ----------------
// grid (ktile=4, qtile=4, bh=128). A=Q rows lda=3E, B=K rows ldb=3E. K=64 -> 6 chunks.
__global__ __launch_bounds__(256, 2) void scores_mma(
    const __nv_bfloat16* __restrict__ qh, const __nv_bfloat16* __restrict__ ql,
    float* __restrict__ sc)
{
    extern __shared__ __align__(128) uint8_t dsm[];
    const int tid = threadIdx.x;
    const uint32_t sbase = smem_u32(dsm);
    const int wid = tid >> 5, lane = tid & 31;
    const int wm = wid >> 1, wn = wid & 1;
    const int bh = blockIdx.z, b = bh >> 4, h = bh & 15;
    const int LDQ = 3 * En;

    const __nv_bfloat16* Qhb = qh + (size_t)b * Tn * LDQ + h * Dn + (size_t)blockIdx.y * 128 * LDQ;
    const __nv_bfloat16* Qlb = ql + (size_t)b * Tn * LDQ + h * Dn + (size_t)blockIdx.y * 128 * LDQ;
    const __nv_bfloat16* Khb = qh + (size_t)b * Tn * LDQ + En + h * Dn + (size_t)blockIdx.x * 128 * LDQ;
    const __nv_bfloat16* Klb = ql + (size_t)b * Tn * LDQ + En + h * Dn + (size_t)blockIdx.x * 128 * LDQ;

    auto load_chunk = [&](int c, int st) {
        int seg = (c >= 2) + (c >= 4);
        int kc = (c - seg * 2) * BK;
        const __nv_bfloat16* Ap = (seg == 1 ? Qlb : Qhb) + kc;
        const __nv_bfloat16* Bp = (seg == 2 ? Klb : Khb) + kc;
        uint32_t sA = sbase + (uint32_t)st * STGB;
        uint32_t sB = sA + 128 * 64;
#pragma unroll
        for (int j = 0; j < 2; j++) {
            int idx = tid + j * 256;
            int r = idx >> 2, cc = idx & 3;
            uint32_t off = r * 64 + ((cc ^ ((r >> 1) & 3)) << 4);
            cpasync16(sA + off, Ap + (size_t)r * LDQ + cc * 8);
        }
#pragma unroll
        for (int j = 0; j < 2; j++) {
            int idx = tid + j * 256;
            int r = idx >> 2, cc = idx & 3;
            uint32_t off = r * 64 + ((cc ^ ((r >> 1) & 3)) << 4);
            cpasync16(sB + off, Bp + (size_t)r * LDQ + cc * 8);
        }
        cp_commit();
    };

    float acc[2][8][4] = {};
    load_chunk(0, 0);
    load_chunk(1, 1);
    load_chunk(2, 2);

    const int C = 6;
    for (int c = 0; c < C; c++) {
        if (c < C - 2)      cp_wait<2>();
        else if (c == C - 2) cp_wait<1>();
        else                 cp_wait<0>();
        __syncthreads();
        if (c + 3 < C) load_chunk(c + 3, (c + 3) & 3);

        uint32_t sA = sbase + (uint32_t)(c & 3) * STGB;
        uint32_t sB = sA + 128 * 64;
#pragma unroll
        for (int ks = 0; ks < 2; ks++) {
            uint32_t af[2][4];
#pragma unroll
            for (int ti = 0; ti < 2; ti++) {
                int r = wm * 32 + ti * 16 + (lane & 15);
                int cc = 2 * ks + (lane >> 4);
                ldsm4(af[ti][0], af[ti][1], af[ti][2], af[ti][3],
                      sA + r * 64 + ((cc ^ ((r >> 1) & 3)) << 4));
            }
#pragma unroll
            for (int tj = 0; tj < 4; tj++) {
                uint32_t b0, b1, b2, b3;
                int r = wn * 64 + tj * 16 + (lane & 15);
                int cc = 2 * ks + (lane >> 4);
                ldsm4(b0, b1, b2, b3, sB + r * 64 + ((cc ^ ((r >> 1) & 3)) << 4));
                mma16816(acc[0][2 * tj],     af[0], b0, b2);
                mma16816(acc[0][2 * tj + 1], af[0], b1, b3);
                mma16816(acc[1][2 * tj],     af[1], b0, b2);
                mma16816(acc[1][2 * tj + 1], af[1], b1, b3);
            }
        }
    }

    float* outb = sc + (size_t)bh * Tn * Tn + blockIdx.x * 128;
    const int col0 = wn * 64;
    const int row0 = blockIdx.y * 128 + wm * 32;
#pragma unroll
    for (int ti = 0; ti < 2; ti++) {
#pragma unroll
        for (int tj = 0; tj < 8; tj++) {
            int cl = col0 + tj * 8 + 2 * (lane & 3);
#pragma unroll
            for (int hh = 0; hh < 2; hh++) {
                int row = row0 + ti * 16 + (lane >> 2) + hh * 8;
                *(float2*)(outb + (size_t)row * Tn + cl) =
                    make_float2(acc[ti][tj][2 * hh] * 0.125f, acc[ti][tj][2 * hh + 1] * 0.125f);
            }
        }
    }
}

// ---------------- softmax * gaussian * renorm -> bf16 hi/lo probs ----------------
__global__ __launch_bounds__(256) void softmax_gauss(
    const float* __restrict__ sc,
    __nv_bfloat16* __restrict__ wh, __nv_bfloat16* __restrict__ wl)
{
    const int q = blockIdx.x & (Tn - 1);
    const float* row = sc + (size_t)blockIdx.x * Tn;
    const int tid = threadIdx.x;
    float s0 = row[tid], s1 = row[tid + 256];
    float m = blockMax(fmaxf(s0, s1));
    float p0 = expf(s0 - m), p1 = expf(s1 - m);
    float d0 = (float)(q - tid), d1 = (float)(q - (tid + 256));
    float g0 = expf(-d0 * d0 * (1.0f / 32768.0f));
    float g1 = expf(-d1 * d1 * (1.0f / 32768.0f));
    float Z = blockSum(p0 + p1);
    float G = blockSum(p0 * g0 + p1 * g1);
    float inv = 1.0f / (G + 1e-5f * Z);
    float w0 = p0 * g0 * inv, w1 = p1 * g1 * inv;
    size_t base = (size_t)blockIdx.x * Tn;
    __nv_bfloat16 h0, l0, h1, l1;
    split_hl(w0, h0, l0);
    split_hl(w1, h1, l1);
    wh[base + tid] = h0;       wl[base + tid] = l0;
    wh[base + tid + 256] = h1; wl[base + tid + 256] = l1;
}

// ---------------- attn output: O = W V on tensor cores (hi/lo) ----------------
// grid (qtile=4, bh=128). CTA 128q x 64d, K=512*3 -> 48 chunks of 32.
// A = W [q][k] (lda=Tn), 4-stage cp.async. B = V transposed in smem [d][k],
// double-buffered, filled by LDG + swizzled STS (prefetched one chunk ahead).
__global__ __launch_bounds__(256, 2) void attno_mma(
    const __nv_bfloat16* __restrict__ wh, const __nv_bfloat16* __restrict__ wl,
    const __nv_bfloat16* __restrict__ vh, const __nv_bfloat16* __restrict__ vl,
    __nv_bfloat16* __restrict__ oh, __nv_bfloat16* __restrict__ ol)
{
    extern __shared__ __align__(128) uint8_t dsm[];
    const int tid = threadIdx.x;
    const uint32_t sbase = smem_u32(dsm);       // A: 4 stages x 8KB = 32KB
    const uint32_t bOff = 32768;                // B: 2 x 4KB
    const int wid = tid >> 5, lane = tid & 31;
    const int wm = wid >> 1, wn = wid & 1;      // warp tile 32q x 32d
    const int bh = blockIdx.y, b = bh >> 4, h = bh & 15;
    const int LDQ = 3 * En;

    const __nv_bfloat16* Wh = wh + (size_t)bh * Tn * Tn + (size_t)blockIdx.x * 128 * Tn;
    const __nv_bfloat16* Wl = wl + (size_t)bh * Tn * Tn + (size_t)blockIdx.x * 128 * Tn;
    const __nv_bfloat16* Vhb = vh + (size_t)b * Tn * LDQ + 2 * En + h * Dn;
    const __nv_bfloat16* Vlb = vl + (size_t)b * Tn * LDQ + 2 * En + h * Dn;

    const int vr = tid >> 3;        // 0..31 (k row within chunk)
    const int vc = (tid & 7) * 8;   // d col (8 bf16 per load)

    auto ldgV = [&](int c) -> uint4 {
        int seg = c >> 4;
        int kc = (c & 15) * BK;
        const __nv_bfloat16* p = (seg == 2 ? Vlb : Vhb) + (size_t)(kc + vr) * LDQ + vc;
        return *(const uint4*)p;
    };
    auto loadA = [&](int c, int st) {
        int seg = c >> 4;
        int kc = (c & 15) * BK;
        const __nv_bfloat16* Ap = (seg == 1 ? Wl : Wh) + kc;
        uint32_t sA = sbase + (uint32_t)st * 8192;
#pragma unroll
        for (int j = 0; j < 2; j++) {
            int idx = tid + j * 256;
            int r = idx >> 2, cc = idx & 3;
            uint32_t off = r * 64 + ((cc ^ ((r >> 1) & 3)) << 4);
            cpasync16(sA + off, Ap + (size_t)r * Tn + cc * 8);
        }
        cp_commit();
    };

    const int C = 48;
    uint4 vreg = ldgV(0);
    loadA(0, 0); loadA(1, 1); loadA(2, 2);

    float acc[2][4][4] = {};

    for (int c = 0; c < C; c++) {
        // transpose-store V chunk into B[c&1]: smem row=d (64B = 32 k x 2B)
        {
            uint32_t w4[4] = {vreg.x, vreg.y, vreg.z, vreg.w};
            uint32_t bb = bOff + (uint32_t)(c & 1) * 4096;
#pragma unroll
            for (int i = 0; i < 8; i++) {
                uint16_t hv = (uint16_t)(w4[i >> 1] >> ((i & 1) * 16));
                int d = vc + i;
                int fd = ((d >> 1) & 3) ^ ((d >> 3) & 3);
                uint32_t off = d * 64 + (((vr >> 3) ^ fd) << 4) + (vr & 7) * 2;
                *(uint16_t*)(dsm + bb + off) = hv;
            }
        }
        if (c + 1 < C) vreg = ldgV(c + 1);
        if (c < C - 2)      cp_wait<2>();
        else if (c == C - 2) cp_wait<1>();
        else                 cp_wait<0>();
        __syncthreads();
        if (c + 3 < C) loadA(c + 3, (c + 3) & 3);

        uint32_t sA = sbase + (uint32_t)(c & 3) * 8192;
        uint32_t sB = sbase + bOff + (uint32_t)(c & 1) * 4096;
#pragma unroll
        for (int ks = 0; ks < 2; ks++) {
            uint32_t af[2][4];
#pragma unroll
            for (int ti = 0; ti < 2; ti++) {
                int r = wm * 32 + ti * 16 + (lane & 15);
                int cc = 2 * ks + (lane >> 4);
                ldsm4(af[ti][0], af[ti][1], af[ti][2], af[ti][3],
                      sA + r * 64 + ((cc ^ ((r >> 1) & 3)) << 4));
            }
#pragma unroll
            for (int tj = 0; tj < 2; tj++) {
                uint32_t b0, b1, b2, b3;
                int r = wn * 32 + tj * 16 + (lane & 15);
                int cc = 2 * ks + (lane >> 4);
                int fd = ((r >> 1) & 3) ^ ((r >> 3) & 3);
                ldsm4(b0, b1, b2, b3, sB + r * 64 + ((cc ^ fd) << 4));
                mma16816(acc[0][2 * tj],     af[0], b0, b2);
                mma16816(acc[0][2 * tj + 1], af[0], b1, b3);
                mma16816(acc[1][2 * tj],     af[1], b0, b2);
                mma16816(acc[1][2 * tj + 1], af[1], b1, b3);
            }
        }
    }

    // epilogue: write hi/lo O into attn buffers [b][t][h*64+d]
#pragma unroll
    for (int ti = 0; ti < 2; ti++) {
#pragma unroll
        for (int tj = 0; tj < 4; tj++) {
            int dl = wn * 32 + tj * 8 + 2 * (lane & 3);
            int colg = h * Dn + dl;
#pragma unroll
            for (int hh = 0; hh < 2; hh++) {
                int row = blockIdx.x * 128 + wm * 32 + ti * 16 + (lane >> 2) + hh * 8;
                float v0 = acc[ti][tj][2 * hh + 0];
                float v1 = acc[ti][tj][2 * hh + 1];
                __nv_bfloat16 h0, l0, h1, l1;
                split_hl(v0, h0, l0);
                split_hl(v1, h1, l1);
                __nv_bfloat162 hv; hv.x = h0; hv.y = h1;
                __nv_bfloat162 lv; lv.x = l0; lv.y = l1;
                size_t o = (size_t)b * Tn * En + (size_t)row * En + colg;
                *(__nv_bfloat162*)(oh + o) = hv;
                *(__nv_bfloat162*)(ol + o) = lv;
            }
        }
    }
}

// ---------------- residual + LN ----------------
__global__ __launch_bounds__(256) void add_ln(
    float* __restrict__ x, const float* __restrict__ r,
    const float* __restrict__ g, const float* __restrict__ bt,
    __nv_bfloat16* __restrict__ xh, __nv_bfloat16* __restrict__ xl)
{
    const size_t base = (size_t)blockIdx.x * En;
    const int tid = threadIdx.x;
    float v[4];
#pragma unroll
    for (int i = 0; i < 4; i++) { int c = tid + i * 256; v[i] = x[base + c] + r[base + c]; }
    float mu = blockSum(v[0] + v[1] + v[2] + v[3]) * (1.0f / En);
    float var = 0.f;
#pragma unroll
    for (int i = 0; i < 4; i++) { float d = v[i] - mu; var += d * d; }
    var = blockSum(var) * (1.0f / En);
    float rs = rsqrtf(var + 1e-5f);
#pragma unroll
    for (int i = 0; i < 4; i++) {
        int c = tid + i * 256;
        float o = (v[i] - mu) * rs * g[c] + bt[c];
        x[base + c] = o;
        split_hl(o, xh[base + c], xl[base + c]);
    }
}

__global__ __launch_bounds__(256) void head_kernel(
    const float* __restrict__ x, const float* __restrict__ hw,
    const float* __restrict__ hb, float* __restrict__ out)
{
    const int b = blockIdx.x;
    const int tid = threadIdx.x;
    const float* row = x + (size_t)b * Tn * En + (size_t)(Tn - 1) * En;
    float s = 0.f;
    for (int c = tid; c < En; c += 256) s += row[c] * hw[c];
    s = blockSum(s);
    if (tid == 0) out[b] = s + hb[0];
}

// ---------------- launch ----------------
extern "C" void kernel_launch(void* const* d_in, const int* in_sizes, int n_in,
                              void* d_out, int out_size)
{
    const float* src    = (const float*)d_in[0];
    const float* in_w   = (const float*)d_in[1];
    const float* in_b   = (const float*)d_in[2];
    const float* outp_w = (const float*)d_in[3];
    const float* outp_b = (const float*)d_in[4];
    const float* ff1_w  = (const float*)d_in[5];
    const float* ff1_b  = (const float*)d_in[6];
    const float* ff2_w  = (const float*)d_in[7];
    const float* ff2_b  = (const float*)d_in[8];
    const float* ln1_g  = (const float*)d_in[9];
    const float* ln1_b  = (const float*)d_in[10];
    const float* ln2_g  = (const float*)d_in[11];
    const float* ln2_b  = (const float*)d_in[12];
    const float* head_w = (const float*)d_in[13];
    const float* head_b = (const float*)d_in[14];
    float* out = (float*)d_out;

    static bool init = false;
    static float *x, *sc, *proj;
    static __nv_bfloat16 *xh,*xl,*ah,*al,*fh,*fl,*qkvh,*qkvl,*wprh,*wprl,
                         *wih,*wil,*woh,*wol,*w1h,*w1l,*w2h,*w2l;
    if (!init) {
        cudaGetSymbolAddress((void**)&x, g_x);
        cudaGetSymbolAddress((void**)&sc, g_scores);
        cudaGetSymbolAddress((void**)&proj, g_proj);
        cudaGetSymbolAddress((void**)&xh, g_xh); cudaGetSymbolAddress((void**)&xl, g_xl);
        cudaGetSymbolAddress((void**)&ah, g_ah); cudaGetSymbolAddress((void**)&al, g_al);
        cudaGetSymbolAddress((void**)&fh, g_fh); cudaGetSymbolAddress((void**)&fl, g_fl);
        cudaGetSymbolAddress((void**)&qkvh, g_qkvh); cudaGetSymbolAddress((void**)&qkvl, g_qkvl);
        cudaGetSymbolAddress((void**)&wprh, g_wprh); cudaGetSymbolAddress((void**)&wprl, g_wprl);
        cudaGetSymbolAddress((void**)&wih, g_wih); cudaGetSymbolAddress((void**)&wil, g_wil);
        cudaGetSymbolAddress((void**)&woh, g_woh); cudaGetSymbolAddress((void**)&wol, g_wol);
        cudaGetSymbolAddress((void**)&w1h, g_w1h); cudaGetSymbolAddress((void**)&w1l, g_w1l);
        cudaGetSymbolAddress((void**)&w2h, g_w2h); cudaGetSymbolAddress((void**)&w2l, g_w2l);
        cudaFuncSetAttribute(gemm_mma, cudaFuncAttributeMaxDynamicSharedMemorySize, 4 * STGB);
        cudaFuncSetAttribute(scores_mma, cudaFuncAttributeMaxDynamicSharedMemorySize, 4 * STGB);
        cudaFuncSetAttribute(attno_mma, cudaFuncAttributeMaxDynamicSharedMemorySize, 40960);
        init = true;
    }

    // weight -> hi/lo bf16 (vectorized)
    convert_hl4<<<Ln * 3 * En * En / 1024, 256>>>((const float4*)in_w,
        (__nv_bfloat162*)wih, (__nv_bfloat162*)wil);
    convert_hl4<<<Ln * En * En / 1024, 256>>>((const float4*)outp_w,
        (__nv_bfloat162*)woh, (__nv_bfloat162*)wol);
    convert_hl4<<<Ln * FFn * En / 1024, 256>>>((const float4*)ff1_w,
        (__nv_bfloat162*)w1h, (__nv_bfloat162*)w1l);
    convert_hl4<<<Ln * En * FFn / 1024, 256>>>((const float4*)ff2_w,
        (__nv_bfloat162*)w2h, (__nv_bfloat162*)w2l);

    pe_add_kernel<<<Bn * Tn * En / 256, 256>>>(src, x, xh, xl);

    for (int l = 0; l < Ln; l++) {
        size_t wo3 = (size_t)l * 3 * En * En, wo1 = (size_t)l * En * En;
        size_t wof = (size_t)l * FFn * En;
        // qkv (bf16 hi/lo out only)
        gemm_mma<<<dim3(3 * En / BN, Bn * Tn / BM), 256, 4 * STGB>>>(
            xh, xl, wih + wo3, wil + wo3, in_b + (size_t)l * 3 * En,
            nullptr, qkvh, qkvl, En, 3 * En, 0);
        // scores (tensor cores)
        scores_mma<<<dim3(4, 4, Bn * Hn), 256, 4 * STGB>>>(qkvh, qkvl, sc);
        // softmax -> bf16 hi/lo probs
        softmax_gauss<<<Bn * Hn * Tn, 256>>>(sc, wprh, wprl);
        // O = W V (tensor cores)
        attno_mma<<<dim3(4, Bn * Hn), 256, 40960>>>(wprh, wprl, qkvh, qkvl, ah, al);
        // out proj
        gemm_mma<<<dim3(En / BN, Bn * Tn / BM), 256, 4 * STGB>>>(
            ah, al, woh + wo1, wol + wo1, outp_b + (size_t)l * En,
            proj, nullptr, nullptr, En, En, 0);
        add_ln<<<Bn * Tn, 256>>>(x, proj, ln1_g + (size_t)l * En, ln1_b + (size_t)l * En, xh, xl);
        // ff1 (relu, hl out)
        gemm_mma<<<dim3(FFn / BN, Bn * Tn / BM), 256, 4 * STGB>>>(
            xh, xl, w1h + wof, w1l + wof, ff1_b + (size_t)l * FFn,
            nullptr, fh, fl, En, FFn, 1);
        // ff2
        gemm_mma<<<dim3(En / BN, Bn * Tn / BM), 256, 4 * STGB>>>(
            fh, fl, w2h + wof, w2l + wof, ff2_b + (size_t)l * En,
            proj, nullptr, nullptr, FFn, En, 0);
        add_ln<<<Bn * Tn, 256>>>(x, proj, ln2_g + (size_t)l * En, ln2_b + (size_t)l * En, xh, xl);
    }

    head_kernel<<<Bn, 256>>>(x, head_w, head_b, out);
}

// round 7
// speedup vs baseline: 2.5390x; 1.2040x over previous
#include <cuda_runtime.h>
#include <cuda_bf16.h>
#include <math.h>
#include <stdint.h>

#define Bn  8
#define Tn  512
#define En  1024
#define Hn  16
#define Dn  64
#define Ln  4
#define FFn 4096

// fp32 scratch
__device__ float g_x[Bn * Tn * En];
__device__ float g_scores[Bn * Hn * Tn * Tn];
__device__ float g_proj[Bn * Tn * En];
// bf16 hi/lo activation pairs
__device__ __nv_bfloat16 g_xh[Bn * Tn * En],  g_xl[Bn * Tn * En];
__device__ __nv_bfloat16 g_ah[Bn * Tn * En],  g_al[Bn * Tn * En];
__device__ __nv_bfloat16 g_fh[Bn * Tn * FFn], g_fl[Bn * Tn * FFn];
__device__ __nv_bfloat16 g_qkvh[Bn * Tn * 3 * En], g_qkvl[Bn * Tn * 3 * En];
__device__ __nv_bfloat16 g_wprh[Bn * Hn * Tn * Tn], g_wprl[Bn * Hn * Tn * Tn];
// bf16 hi/lo weight pairs
__device__ __nv_bfloat16 g_wih[Ln * 3 * En * En], g_wil[Ln * 3 * En * En];
__device__ __nv_bfloat16 g_woh[Ln * En * En],     g_wol[Ln * En * En];
__device__ __nv_bfloat16 g_w1h[Ln * FFn * En],    g_w1l[Ln * FFn * En];
__device__ __nv_bfloat16 g_w2h[Ln * En * FFn],    g_w2l[Ln * En * FFn];

// ---------------- PTX helpers (sm_80+ only) ----------------
__device__ __forceinline__ uint32_t smem_u32(const void* p) {
    uint32_t a;
    asm("{ .reg .u64 t; cvta.to.shared.u64 t, %1; cvt.u32.u64 %0, t; }" : "=r"(a) : "l"(p));
    return a;
}
__device__ __forceinline__ void cpasync16(uint32_t dst, const void* src) {
    asm volatile("cp.async.cg.shared.global [%0], [%1], 16;" :: "r"(dst), "l"(src));
}
__device__ __forceinline__ void cp_commit() { asm volatile("cp.async.commit_group;" ::: "memory"); }
template <int N> __device__ __forceinline__ void cp_wait() {
    asm volatile("cp.async.wait_group %0;" :: "n"(N) : "memory");
}
__device__ __forceinline__ void ldsm4(uint32_t& r0, uint32_t& r1, uint32_t& r2,
                                      uint32_t& r3, uint32_t a) {
    asm volatile("ldmatrix.sync.aligned.m8n8.x4.shared.b16 {%0,%1,%2,%3}, [%4];"
                 : "=r"(r0), "=r"(r1), "=r"(r2), "=r"(r3) : "r"(a));
}
__device__ __forceinline__ void mma16816(float* d, const uint32_t* a, uint32_t b0, uint32_t b1) {
    asm volatile("mma.sync.aligned.m16n8k16.row.col.f32.bf16.bf16.f32 "
                 "{%0,%1,%2,%3}, {%4,%5,%6,%7}, {%8,%9}, {%0,%1,%2,%3};"
                 : "+f"(d[0]), "+f"(d[1]), "+f"(d[2]), "+f"(d[3])
                 : "r"(a[0]), "r"(a[1]), "r"(a[2]), "r"(a[3]), "r"(b0), "r"(b1));
}
__device__ __forceinline__ void split_hl(float v, __nv_bfloat16& h, __nv_bfloat16& l) {
    h = __float2bfloat16(v);
    l = __float2bfloat16(v - __bfloat162float(h));
}

// ---------------- reductions ----------------
__device__ __forceinline__ float warpSum(float v) {
#pragma unroll
    for (int o = 16; o; o >>= 1) v += __shfl_xor_sync(~0u, v, o);
    return v;
}
__device__ __forceinline__ float warpMax(float v) {
#pragma unroll
    for (int o = 16; o; o >>= 1) v = fmaxf(v, __shfl_xor_sync(~0u, v, o));
    return v;
}
__device__ __forceinline__ float blockSum(float v) {
    __shared__ float sm[8];
    int lane = threadIdx.x & 31, wid = threadIdx.x >> 5;
    v = warpSum(v);
    __syncthreads();
    if (lane == 0) sm[wid] = v;
    __syncthreads();
    v = sm[lane & 7];
#pragma unroll
    for (int o = 4; o; o >>= 1) v += __shfl_xor_sync(~0u, v, o);
    return v;
}
__device__ __forceinline__ float blockMax(float v) {
    __shared__ float sm[8];
    int lane = threadIdx.x & 31, wid = threadIdx.x >> 5;
    v = warpMax(v);
    __syncthreads();
    if (lane == 0) sm[wid] = v;
    __syncthreads();
    v = sm[lane & 7];
#pragma unroll
    for (int o = 4; o; o >>= 1) v = fmaxf(v, __shfl_xor_sync(~0u, v, o));
    return v;
}
// sum two values in one reduction round
__device__ __forceinline__ float2 blockSum2(float a, float b) {
    __shared__ float2 sm[8];
    int lane = threadIdx.x & 31, wid = threadIdx.x >> 5;
#pragma unroll
    for (int o = 16; o; o >>= 1) {
        a += __shfl_xor_sync(~0u, a, o);
        b += __shfl_xor_sync(~0u, b, o);
    }
    __syncthreads();
    if (lane == 0) sm[wid] = make_float2(a, b);
    __syncthreads();
    float2 v = sm[lane & 7];
#pragma unroll
    for (int o = 4; o; o >>= 1) {
        v.x += __shfl_xor_sync(~0u, v.x, o);
        v.y += __shfl_xor_sync(~0u, v.y, o);
    }
    return v;
}

// ---------------- small kernels ----------------
__global__ void convert_hl4(const float4* __restrict__ s,
                            __nv_bfloat162* __restrict__ h,
                            __nv_bfloat162* __restrict__ l) {
    int i = blockIdx.x * 256 + threadIdx.x;
    float4 v = s[i];
    __nv_bfloat16 h0,l0,h1,l1,h2,l2,h3,l3;
    split_hl(v.x, h0, l0); split_hl(v.y, h1, l1);
    split_hl(v.z, h2, l2); split_hl(v.w, h3, l3);
    __nv_bfloat162 a, b, c, d;
    a.x = h0; a.y = h1; b.x = h2; b.y = h3;
    c.x = l0; c.y = l1; d.x = l2; d.y = l3;
    h[2*i] = a; h[2*i+1] = b;
    l[2*i] = c; l[2*i+1] = d;
}

__global__ void pe_add_kernel(const float* __restrict__ src, float* __restrict__ x,
                              __nv_bfloat16* __restrict__ xh, __nv_bfloat16* __restrict__ xl) {
    int idx = blockIdx.x * 256 + threadIdx.x;
    int e = idx & (En - 1);
    int b = idx / (Tn * En);
    float dv = expf((float)(e & ~1) * (-9.210340371976184f / (float)En));
    float ang = (float)b * dv;
    float pe = (e & 1) ? cosf(ang) : sinf(ang);
    float v = src[idx] + pe;
    x[idx] = v;
    split_hl(v, xh[idx], xl[idx]);
}

// ---------------- fused hi/lo bf16 GEMM (single K pass, 3 MMA combos) ----------------
// C[4096, N] = (Ah+Al)[4096,K] @ (Bh+Bl)[N,K]^T + bias  (AlBl dropped, ~2^-16)
// CTA 128x128, BK=32; per chunk load Ah,Al,Bh,Bl tiles (32 KB stage), 3-stage pipe.
#define BM 128
#define BN 128
#define BK 32
#define RGB 8192                    // one 128x32 bf16 region
#define STGB (4 * RGB)              // 32 KB per stage

__global__ __launch_bounds__(256, 2) void gemm_mma(
    const __nv_bfloat16* __restrict__ Ah, const __nv_bfloat16* __restrict__ Al,
    const __nv_bfloat16* __restrict__ Bh, const __nv_bfloat16* __restrict__ Bl,
    const float* __restrict__ bias, float* __restrict__ Cf,
    __nv_bfloat16* __restrict__ Ch, __nv_bfloat16* __restrict__ Cl,
    int K, int N, int relu)
{
    extern __shared__ __align__(128) uint8_t dsm[];
    __shared__ float sh_bias[BN];

    const int tid = threadIdx.x;
    const uint32_t sbase = smem_u32(dsm);
    if (tid < BN) sh_bias[tid] = bias[blockIdx.x * BN + tid];

    const int wid = tid >> 5, lane = tid & 31;
    const int wm = wid >> 1, wn = wid & 1;

    const __nv_bfloat16* Abh = Ah + (size_t)blockIdx.y * BM * K;
    const __nv_bfloat16* Abl = Al + (size_t)blockIdx.y * BM * K;
    const __nv_bfloat16* Bbh = Bh + (size_t)blockIdx.x * BN * K;
    const __nv_bfloat16* Bbl = Bl + (size_t)blockIdx.x * BN * K;

    const int cps = K / BK;

    auto load_chunk = [&](int c, int st) {
        int kc = c * BK;
        uint32_t sg = sbase + (uint32_t)st * STGB;
#pragma unroll
        for (int j = 0; j < 2; j++) {
            int idx = tid + j * 256;
            int r = idx >> 2, cc = idx & 3;
            uint32_t off = r * 64 + ((cc ^ ((r >> 1) & 3)) << 4);
            size_t go = (size_t)r * K + kc + cc * 8;
            cpasync16(sg + off,            Abh + go);
            cpasync16(sg + RGB + off,      Abl + go);
            cpasync16(sg + 2 * RGB + off,  Bbh + go);
            cpasync16(sg + 3 * RGB + off,  Bbl + go);
        }
        cp_commit();
    };

    float acc[2][8][4] = {};
    load_chunk(0, 0);
    load_chunk(1, 1);

    int st = 0;
    for (int c = 0; c < cps; c++) {
        if (c + 1 < cps) cp_wait<1>(); else cp_wait<0>();
        __syncthreads();
        if (c + 2 < cps) {
            int ns = st + 2; if (ns >= 3) ns -= 3;
            load_chunk(c + 2, ns);
        }

        uint32_t sAh = sbase + (uint32_t)st * STGB;
        uint32_t sAl = sAh + RGB;
        uint32_t sBh = sAh + 2 * RGB;
        uint32_t sBl = sAh + 3 * RGB;
#pragma unroll
        for (int ks = 0; ks < 2; ks++) {
            uint32_t ah[2][4], al[2][4];
#pragma unroll
            for (int ti = 0; ti < 2; ti++) {
                int r = wm * 32 + ti * 16 + (lane & 15);
                int cc = 2 * ks + (lane >> 4);
                uint32_t off = r * 64 + ((cc ^ ((r >> 1) & 3)) << 4);
                ldsm4(ah[ti][0], ah[ti][1], ah[ti][2], ah[ti][3], sAh + off);
                ldsm4(al[ti][0], al[ti][1], al[ti][2], al[ti][3], sAl + off);
            }
#pragma unroll
            for (int tj = 0; tj < 4; tj++) {
                int r = wn * 64 + tj * 16 + (lane & 15);
                int cc = 2 * ks + (lane >> 4);
                uint32_t off = r * 64 + ((cc ^ ((r >> 1) & 3)) << 4);
                uint32_t b0, b1, b2, b3, c0, c1, c2, c3;
                ldsm4(b0, b1, b2, b3, sBh + off);
                ldsm4(c0, c1, c2, c3, sBl + off);
                // hi*hi
                mma16816(acc[0][2 * tj],     ah[0], b0, b2);
                mma16816(acc[0][2 * tj + 1], ah[0], b1, b3);
                mma16816(acc[1][2 * tj],     ah[1], b0, b2);
                mma16816(acc[1][2 * tj + 1], ah[1], b1, b3);
                // lo*hi
                mma16816(acc[0][2 * tj],     al[0], b0, b2);
                mma16816(acc[0][2 * tj + 1], al[0], b1, b3);
                mma16816(acc[1][2 * tj],     al[1], b0, b2);
                mma16816(acc[1][2 * tj + 1], al[1], b1, b3);
                // hi*lo
                mma16816(acc[0][2 * tj],     ah[0], c0, c2);
                mma16816(acc[0][2 * tj + 1], ah[0], c1, c3);
                mma16816(acc[1][2 * tj],     ah[1], c0, c2);
                mma16816(acc[1][2 * tj + 1], ah[1], c1, c3);
            }
        }
        if (++st == 3) st = 0;
    }

    const int col0 = wn * 64;
    const int row0 = blockIdx.y * BM + wm * 32;
#pragma unroll
    for (int ti = 0; ti < 2; ti++) {
#pragma unroll
        for (int tj = 0; tj < 8; tj++) {
            int cl = col0 + tj * 8 + 2 * (lane & 3);
            int colg = blockIdx.x * BN + cl;
            float b0 = sh_bias[cl], b1 = sh_bias[cl + 1];
#pragma unroll
            for (int hh = 0; hh < 2; hh++) {
                int row = row0 + ti * 16 + (lane >> 2) + hh * 8;
                float v0 = acc[ti][tj][2 * hh + 0] + b0;
                float v1 = acc[ti][tj][2 * hh + 1] + b1;
                if (relu) { v0 = fmaxf(v0, 0.f); v1 = fmaxf(v1, 0.f); }
                size_t o = (size_t)row * N + colg;
                if (Cf) *(float2*)(Cf + o) = make_float2(v0, v1);
                if (Ch) {
                    __nv_bfloat16 h0, l0, h1, l1;
                    split_hl(v0, h0, l0);
                    split_hl(v1, h1, l1);
                    __nv_bfloat162 hv; hv.x = h0; hv.y = h1;
                    __nv_bfloat162 lv; lv.x = l0; lv.y = l1;
                    *(__nv_bfloat162*)(Ch + o) = hv;
                    *(__nv_bfloat162*)(Cl + o) = lv;
                }
            }
        }
    }
}

// ---------------- scores: S = Q K^T / 8 (fused hi/lo, K=64 -> 2 chunks) ----------------
__global__ __launch_bounds__(256, 2) void scores_mma(
    const __nv_bfloat16* __restrict__ qh, const __nv_bfloat16* __restrict__ ql,
    float* __restrict__ sc)
{
    extern __shared__ __align__(128) uint8_t dsm[];
    const int tid = threadIdx.x;
    const uint32_t sbase = smem_u32(dsm);
    const int wid = tid >> 5, lane = tid & 31;
    const int wm = wid >> 1, wn = wid & 1;
    const int bh = blockIdx.z, b = bh >> 4, h = bh & 15;
    const int LDQ = 3 * En;

    const __nv_bfloat16* Qhb = qh + (size_t)b * Tn * LDQ + h * Dn + (size_t)blockIdx.y * 128 * LDQ;
    const __nv_bfloat16* Qlb = ql + (size_t)b * Tn * LDQ + h * Dn + (size_t)blockIdx.y * 128 * LDQ;
    const __nv_bfloat16* Khb = qh + (size_t)b * Tn * LDQ + En + h * Dn + (size_t)blockIdx.x * 128 * LDQ;
    const __nv_bfloat16* Klb = ql + (size_t)b * Tn * LDQ + En + h * Dn + (size_t)blockIdx.x * 128 * LDQ;

    auto load_chunk = [&](int c, int stg) {
        int kc = c * BK;
        uint32_t sg = sbase + (uint32_t)stg * STGB;
#pragma unroll
        for (int j = 0; j < 2; j++) {
            int idx = tid + j * 256;
            int r = idx >> 2, cc = idx & 3;
            uint32_t off = r * 64 + ((cc ^ ((r >> 1) & 3)) << 4);
            size_t go = (size_t)r * LDQ + kc + cc * 8;
            cpasync16(sg + off,           Qhb + go);
            cpasync16(sg + RGB + off,     Qlb + go);
            cpasync16(sg + 2 * RGB + off, Khb + go);
            cpasync16(sg + 3 * RGB + off, Klb + go);
        }
        cp_commit();
    };

    float acc[2][8][4] = {};
    load_chunk(0, 0);
    load_chunk(1, 1);

    for (int c = 0; c < 2; c++) {
        if (c == 0) cp_wait<1>(); else cp_wait<0>();
        __syncthreads();
        uint32_t sAh = sbase + (uint32_t)c * STGB;
        uint32_t sAl = sAh + RGB;
        uint32_t sBh = sAh + 2 * RGB;
        uint32_t sBl = sAh + 3 * RGB;
#pragma unroll
        for (int ks = 0; ks < 2; ks++) {
            uint32_t ah[2][4], al[2][4];
#pragma unroll
            for (int ti = 0; ti < 2; ti++) {
                int r = wm * 32 + ti * 16 + (lane & 15);
                int cc = 2 * ks + (lane >> 4);
                uint32_t off = r * 64 + ((cc ^ ((r >> 1) & 3)) << 4);
                ldsm4(ah[ti][0], ah[ti][1], ah[ti][2], ah[ti][3], sAh + off);
                ldsm4(al[ti][0], al[ti][1], al[ti][2], al[ti][3], sAl + off);
            }
#pragma unroll
            for (int tj = 0; tj < 4; tj++) {
                int r = wn * 64 + tj * 16 + (lane & 15);
                int cc = 2 * ks + (lane >> 4);
                uint32_t off = r * 64 + ((cc ^ ((r >> 1) & 3)) << 4);
                uint32_t b0, b1, b2, b3, c0, c1, c2, c3;
                ldsm4(b0, b1, b2, b3, sBh + off);
                ldsm4(c0, c1, c2, c3, sBl + off);
                mma16816(acc[0][2 * tj],     ah[0], b0, b2);
                mma16816(acc[0][2 * tj + 1], ah[0], b1, b3);
                mma16816(acc[1][2 * tj],     ah[1], b0, b2);
                mma16816(acc[1][2 * tj + 1], ah[1], b1, b3);
                mma16816(acc[0][2 * tj],     al[0], b0, b2);
                mma16816(acc[0][2 * tj + 1], al[0], b1, b3);
                mma16816(acc[1][2 * tj],     al[1], b0, b2);
                mma16816(acc[1][2 * tj + 1], al[1], b1, b3);
                mma16816(acc[0][2 * tj],     ah[0], c0, c2);
                mma16816(acc[0][2 * tj + 1], ah[0], c1, c3);
                mma16816(acc[1][2 * tj],     ah[1], c0, c2);
                mma16816(acc[1][2 * tj + 1], ah[1], c1, c3);
            }
        }
    }

    float* outb = sc + (size_t)bh * Tn * Tn + blockIdx.x * 128;
    const int col0 = wn * 64;
    const int row0 = blockIdx.y * 128 + wm * 32;
#pragma unroll
    for (int ti = 0; ti < 2; ti++) {
#pragma unroll
        for (int tj = 0; tj < 8; tj++) {
            int cl = col0 + tj * 8 + 2 * (lane & 3);
#pragma unroll
            for (int hh = 0; hh < 2; hh++) {
                int row = row0 + ti * 16 + (lane >> 2) + hh * 8;
                *(float2*)(outb + (size_t)row * Tn + cl) =
                    make_float2(acc[ti][tj][2 * hh] * 0.125f, acc[ti][tj][2 * hh + 1] * 0.125f);
            }
        }
    }
}

// ---------------- softmax * gaussian * renorm -> bf16 hi/lo probs ----------------
__global__ __launch_bounds__(256) void softmax_gauss(
    const float* __restrict__ sc,
    __nv_bfloat16* __restrict__ wh, __nv_bfloat16* __restrict__ wl)
{
    const int q = blockIdx.x & (Tn - 1);
    const float* row = sc + (size_t)blockIdx.x * Tn;
    const int tid = threadIdx.x;
    float s0 = row[tid], s1 = row[tid + 256];
    float m = blockMax(fmaxf(s0, s1));
    float p0 = __expf(s0 - m), p1 = __expf(s1 - m);
    float d0 = (float)(q - tid), d1 = (float)(q - (tid + 256));
    float g0 = __expf(-d0 * d0 * (1.0f / 32768.0f));
    float g1 = __expf(-d1 * d1 * (1.0f / 32768.0f));
    float2 zg = blockSum2(p0 + p1, p0 * g0 + p1 * g1);
    float inv = 1.0f / (zg.y + 1e-5f * zg.x);
    float w0 = p0 * g0 * inv, w1 = p1 * g1 * inv;
    size_t base = (size_t)blockIdx.x * Tn;
    __nv_bfloat16 h0, l0, h1, l1;
    split_hl(w0, h0, l0);
    split_hl(w1, h1, l1);
    wh[base + tid] = h0;       wl[base + tid] = l0;
    wh[base + tid + 256] = h1; wl[base + tid + 256] = l1;
}

// ---------------- attn output: O = W V (fused hi/lo, 16 chunks) ----------------
// A stage = Wh 8KB + Wl 8KB, 3 stages (48KB). B buf = Vh 4KB + Vl 4KB, x2 (16KB).
__global__ __launch_bounds__(256, 2) void attno_mma(
    const __nv_bfloat16* __restrict__ wh, const __nv_bfloat16* __restrict__ wl,
    const __nv_bfloat16* __restrict__ vh, const __nv_bfloat16* __restrict__ vl,
    __nv_bfloat16* __restrict__ oh, __nv_bfloat16* __restrict__ ol)
{
    extern __shared__ __align__(128) uint8_t dsm[];
    const int tid = threadIdx.x;
    const uint32_t sbase = smem_u32(dsm);
    const uint32_t bOff = 49152;
    const int wid = tid >> 5, lane = tid & 31;
    const int wm = wid >> 1, wn = wid & 1;
    const int bh = blockIdx.y, b = bh >> 4, h = bh & 15;
    const int LDQ = 3 * En;

    const __nv_bfloat16* Wh = wh + (size_t)bh * Tn * Tn + (size_t)blockIdx.x * 128 * Tn;
    const __nv_bfloat16* Wl = wl + (size_t)bh * Tn * Tn + (size_t)blockIdx.x * 128 * Tn;
    const __nv_bfloat16* Vhb = vh + (size_t)b * Tn * LDQ + 2 * En + h * Dn;
    const __nv_bfloat16* Vlb = vl + (size_t)b * Tn * LDQ + 2 * En + h * Dn;

    const int vr = tid >> 3;
    const int vc = (tid & 7) * 8;

    auto loadA = [&](int c, int stg) {
        int kc = c * BK;
        uint32_t sg = sbase + (uint32_t)stg * 16384;
#pragma unroll
        for (int j = 0; j < 2; j++) {
            int idx = tid + j * 256;
            int r = idx >> 2, cc = idx & 3;
            uint32_t off = r * 64 + ((cc ^ ((r >> 1) & 3)) << 4);
            size_t go = (size_t)r * Tn + kc + cc * 8;
            cpasync16(sg + off,        Wh + go);
            cpasync16(sg + 8192 + off, Wl + go);
        }
        cp_commit();
    };

    const int C = 16;
    uint4 vrh = *(const uint4*)(Vhb + (size_t)vr * LDQ + vc);
    uint4 vrl = *(const uint4*)(Vlb + (size_t)vr * LDQ + vc);
    loadA(0, 0); loadA(1, 1);

    float acc[2][4][4] = {};
    int st = 0;
    for (int c = 0; c < C; c++) {
        // transpose-store V hi/lo chunk into buffer c&1
        {
            uint32_t wh4[4] = {vrh.x, vrh.y, vrh.z, vrh.w};
            uint32_t wl4[4] = {vrl.x, vrl.y, vrl.z, vrl.w};
            uint32_t bb = bOff + (uint32_t)(c & 1) * 8192;
#pragma unroll
            for (int i = 0; i < 8; i++) {
                uint16_t hv = (uint16_t)(wh4[i >> 1] >> ((i & 1) * 16));
                uint16_t lv = (uint16_t)(wl4[i >> 1] >> ((i & 1) * 16));
                int d = vc + i;
                int fd = ((d >> 1) & 3) ^ ((d >> 3) & 3);
                uint32_t off = d * 64 + (((vr >> 3) ^ fd) << 4) + (vr & 7) * 2;
                *(uint16_t*)(dsm + bb + off) = hv;
                *(uint16_t*)(dsm + bb + 4096 + off) = lv;
            }
        }
        if (c + 1 < C) {
            int kc = (c + 1) * BK;
            vrh = *(const uint4*)(Vhb + (size_t)(kc + vr) * LDQ + vc);
            vrl = *(const uint4*)(Vlb + (size_t)(kc + vr) * LDQ + vc);
        }
        if (c + 1 < C) cp_wait<1>(); else cp_wait<0>();
        __syncthreads();
        if (c + 2 < C) {
            int ns = st + 2; if (ns >= 3) ns -= 3;
            loadA(c + 2, ns);
        }

        uint32_t sAh = sbase + (uint32_t)st * 16384;
        uint32_t sAl = sAh + 8192;
        uint32_t sBh = sbase + bOff + (uint32_t)(c & 1) * 8192;
        uint32_t sBl = sBh + 4096;
#pragma unroll
        for (int ks = 0; ks < 2; ks++) {
            uint32_t ah[2][4], al[2][4];
#pragma unroll
            for (int ti = 0; ti < 2; ti++) {
                int r = wm * 32 + ti * 16 + (lane & 15);
                int cc = 2 * ks + (lane >> 4);
                uint32_t off = r * 64 + ((cc ^ ((r >> 1) & 3)) << 4);
                ldsm4(ah[ti][0], ah[ti][1], ah[ti][2], ah[ti][3], sAh + off);
                ldsm4(al[ti][0], al[ti][1], al[ti][2], al[ti][3], sAl + off);
            }
#pragma unroll
            for (int tj = 0; tj < 2; tj++) {
                int r = wn * 32 + tj * 16 + (lane & 15);
                int cc = 2 * ks + (lane >> 4);
                int fd = ((r >> 1) & 3) ^ ((r >> 3) & 3);
                uint32_t off = r * 64 + ((cc ^ fd) << 4);
                uint32_t b0, b1, b2, b3, c0, c1, c2, c3;
                ldsm4(b0, b1, b2, b3, sBh + off);
                ldsm4(c0, c1, c2, c3, sBl + off);
                mma16816(acc[0][2 * tj],     ah[0], b0, b2);
                mma16816(acc[0][2 * tj + 1], ah[0], b1, b3);
                mma16816(acc[1][2 * tj],     ah[1], b0, b2);
                mma16816(acc[1][2 * tj + 1], ah[1], b1, b3);
                mma16816(acc[0][2 * tj],     al[0], b0, b2);
                mma16816(acc[0][2 * tj + 1], al[0], b1, b3);
                mma16816(acc[1][2 * tj],     al[1], b0, b2);
                mma16816(acc[1][2 * tj + 1], al[1], b1, b3);
                mma16816(acc[0][2 * tj],     ah[0], c0, c2);
                mma16816(acc[0][2 * tj + 1], ah[0], c1, c3);
                mma16816(acc[1][2 * tj],     ah[1], c0, c2);
                mma16816(acc[1][2 * tj + 1], ah[1], c1, c3);
            }
        }
        if (++st == 3) st = 0;
    }

#pragma unroll
    for (int ti = 0; ti < 2; ti++) {
#pragma unroll
        for (int tj = 0; tj < 4; tj++) {
            int dl = wn * 32 + tj * 8 + 2 * (lane & 3);
            int colg = h * Dn + dl;
#pragma unroll
            for (int hh = 0; hh < 2; hh++) {
                int row = blockIdx.x * 128 + wm * 32 + ti * 16 + (lane >> 2) + hh * 8;
                float v0 = acc[ti][tj][2 * hh + 0];
                float v1 = acc[ti][tj][2 * hh + 1];
                __nv_bfloat16 h0, l0, h1, l1;
                split_hl(v0, h0, l0);
                split_hl(v1, h1, l1);
                __nv_bfloat162 hv; hv.x = h0; hv.y = h1;
                __nv_bfloat162 lv; lv.x = l0; lv.y = l1;
                size_t o = (size_t)b * Tn * En + (size_t)row * En + colg;
                *(__nv_bfloat162*)(oh + o) = hv;
                *(__nv_bfloat162*)(ol + o) = lv;
            }
        }
    }
}

// ---------------- residual + LN ----------------
__global__ __launch_bounds__(256) void add_ln(
    float* __restrict__ x, const float* __restrict__ r,
    const float* __restrict__ g, const float* __restrict__ bt,
    __nv_bfloat16* __restrict__ xh, __nv_bfloat16* __restrict__ xl)
{
    const size_t base = (size_t)blockIdx.x * En;
    const int tid = threadIdx.x;
    float v[4];
#pragma unroll
    for (int i = 0; i < 4; i++) { int c = tid + i * 256; v[i] = x[base + c] + r[base + c]; }
    float mu = blockSum(v[0] + v[1] + v[2] + v[3]) * (1.0f / En);
    float var = 0.f;
#pragma unroll
    for (int i = 0; i < 4; i++) { float d = v[i] - mu; var += d * d; }
    var = blockSum(var) * (1.0f / En);
    float rs = rsqrtf(var + 1e-5f);
#pragma unroll
    for (int i = 0; i < 4; i++) {
        int c = tid + i * 256;
        float o = (v[i] - mu) * rs * g[c] + bt[c];
        x[base + c] = o;
        split_hl(o, xh[base + c], xl[base + c]);
    }
}

__global__ __launch_bounds__(256) void head_kernel(
    const float* __restrict__ x, const float* __restrict__ hw,
    const float* __restrict__ hb, float* __restrict__ out)
{
    const int b = blockIdx.x;
    const int tid = threadIdx.x;
    const float* row = x + (size_t)b * Tn * En + (size_t)(Tn - 1) * En;
    float s = 0.f;
    for (int c = tid; c < En; c += 256) s += row[c] * hw[c];
    s = blockSum(s);
    if (tid == 0) out[b] = s + hb[0];
}

// ---------------- launch ----------------
extern "C" void kernel_launch(void* const* d_in, const int* in_sizes, int n_in,
                              void* d_out, int out_size)
{
    const float* src    = (const float*)d_in[0];
    const float* in_w   = (const float*)d_in[1];
    const float* in_b   = (const float*)d_in[2];
    const float* outp_w = (const float*)d_in[3];
    const float* outp_b = (const float*)d_in[4];
    const float* ff1_w  = (const float*)d_in[5];
    const float* ff1_b  = (const float*)d_in[6];
    const float* ff2_w  = (const float*)d_in[7];
    const float* ff2_b  = (const float*)d_in[8];
    const float* ln1_g  = (const float*)d_in[9];
    const float* ln1_b  = (const float*)d_in[10];
    const float* ln2_g  = (const float*)d_in[11];
    const float* ln2_b  = (const float*)d_in[12];
    const float* head_w = (const float*)d_in[13];
    const float* head_b = (const float*)d_in[14];
    float* out = (float*)d_out;

    static bool init = false;
    static float *x, *sc, *proj;
    static __nv_bfloat16 *xh,*xl,*ah,*al,*fh,*fl,*qkvh,*qkvl,*wprh,*wprl,
                         *wih,*wil,*woh,*wol,*w1h,*w1l,*w2h,*w2l;
    if (!init) {
        cudaGetSymbolAddress((void**)&x, g_x);
        cudaGetSymbolAddress((void**)&sc, g_scores);
        cudaGetSymbolAddress((void**)&proj, g_proj);
        cudaGetSymbolAddress((void**)&xh, g_xh); cudaGetSymbolAddress((void**)&xl, g_xl);
        cudaGetSymbolAddress((void**)&ah, g_ah); cudaGetSymbolAddress((void**)&al, g_al);
        cudaGetSymbolAddress((void**)&fh, g_fh); cudaGetSymbolAddress((void**)&fl, g_fl);
        cudaGetSymbolAddress((void**)&qkvh, g_qkvh); cudaGetSymbolAddress((void**)&qkvl, g_qkvl);
        cudaGetSymbolAddress((void**)&wprh, g_wprh); cudaGetSymbolAddress((void**)&wprl, g_wprl);
        cudaGetSymbolAddress((void**)&wih, g_wih); cudaGetSymbolAddress((void**)&wil, g_wil);
        cudaGetSymbolAddress((void**)&woh, g_woh); cudaGetSymbolAddress((void**)&wol, g_wol);
        cudaGetSymbolAddress((void**)&w1h, g_w1h); cudaGetSymbolAddress((void**)&w1l, g_w1l);
        cudaGetSymbolAddress((void**)&w2h, g_w2h); cudaGetSymbolAddress((void**)&w2l, g_w2l);
        cudaFuncSetAttribute(gemm_mma, cudaFuncAttributeMaxDynamicSharedMemorySize, 3 * STGB);
        cudaFuncSetAttribute(scores_mma, cudaFuncAttributeMaxDynamicSharedMemorySize, 2 * STGB);
        cudaFuncSetAttribute(attno_mma, cudaFuncAttributeMaxDynamicSharedMemorySize, 65536);
        init = true;
    }

    // weight -> hi/lo bf16
    convert_hl4<<<Ln * 3 * En * En / 1024, 256>>>((const float4*)in_w,
        (__nv_bfloat162*)wih, (__nv_bfloat162*)wil);
    convert_hl4<<<Ln * En * En / 1024, 256>>>((const float4*)outp_w,
        (__nv_bfloat162*)woh, (__nv_bfloat162*)wol);
    convert_hl4<<<Ln * FFn * En / 1024, 256>>>((const float4*)ff1_w,
        (__nv_bfloat162*)w1h, (__nv_bfloat162*)w1l);
    convert_hl4<<<Ln * En * FFn / 1024, 256>>>((const float4*)ff2_w,
        (__nv_bfloat162*)w2h, (__nv_bfloat162*)w2l);

    pe_add_kernel<<<Bn * Tn * En / 256, 256>>>(src, x, xh, xl);

    for (int l = 0; l < Ln; l++) {
        size_t wo3 = (size_t)l * 3 * En * En, wo1 = (size_t)l * En * En;
        size_t wof = (size_t)l * FFn * En;
        // qkv (bf16 hi/lo out only)
        gemm_mma<<<dim3(3 * En / BN, Bn * Tn / BM), 256, 3 * STGB>>>(
            xh, xl, wih + wo3, wil + wo3, in_b + (size_t)l * 3 * En,
            nullptr, qkvh, qkvl, En, 3 * En, 0);
        scores_mma<<<dim3(4, 4, Bn * Hn), 256, 2 * STGB>>>(qkvh, qkvl, sc);
        softmax_gauss<<<Bn * Hn * Tn, 256>>>(sc, wprh, wprl);
        attno_mma<<<dim3(4, Bn * Hn), 256, 65536>>>(wprh, wprl, qkvh, qkvl, ah, al);
        // out proj
        gemm_mma<<<dim3(En / BN, Bn * Tn / BM), 256, 3 * STGB>>>(
            ah, al, woh + wo1, wol + wo1, outp_b + (size_t)l * En,
            proj, nullptr, nullptr, En, En, 0);
        add_ln<<<Bn * Tn, 256>>>(x, proj, ln1_g + (size_t)l * En, ln1_b + (size_t)l * En, xh, xl);
        // ff1 (relu, hl out)
        gemm_mma<<<dim3(FFn / BN, Bn * Tn / BM), 256, 3 * STGB>>>(
            xh, xl, w1h + wof, w1l + wof, ff1_b + (size_t)l * FFn,
            nullptr, fh, fl, En, FFn, 1);
        // ff2
        gemm_mma<<<dim3(En / BN, Bn * Tn / BM), 256, 3 * STGB>>>(
            fh, fl, w2h + wof, w2l + wof, ff2_b + (size_t)l * En,
            proj, nullptr, nullptr, FFn, En, 0);
        add_ln<<<Bn * Tn, 256>>>(x, proj, ln2_g + (size_t)l * En, ln2_b + (size_t)l * En, xh, xl);
    }

    head_kernel<<<Bn, 256>>>(x, head_w, head_b, out);
}